// round 1
// baseline (speedup 1.0000x reference)
#include <cuda_runtime.h>
#include <math.h>

#define BB 4
#define NN 1024
#define DIM 256
#define HH 8
#define HD 32
#define FFN_DIM 1024
#define MROWS (2 * BB * NN)          // 8192 combined rows (src+tgt)
#define STREAM_ELEMS (BB * NN * DIM) // 1048576
#define SCALE 0.17677669529663687f   // 1/sqrt(32)

// ---------------- scratch (static device memory; no allocation) ----------------
__device__ float g_xn[MROWS * DIM];
__device__ float g_q [MROWS * DIM];
__device__ float g_k [MROWS * DIM];
__device__ float g_v [MROWS * DIM];
__device__ float g_ao[MROWS * DIM];
__device__ float g_h [MROWS * FFN_DIM];

// ---------------- residual init: res = feats ----------------
__global__ void copy_feats_kernel(const float4* __restrict__ a,
                                  const float4* __restrict__ b,
                                  float4* __restrict__ out) {
    int i = blockIdx.x * blockDim.x + threadIdx.x;
    out[i] = a[i];
    out[i + STREAM_ELEMS / 4] = b[i];
}

// ---------------- LayerNorm: one block (256 thr) per row ----------------
__global__ __launch_bounds__(256) void ln_kernel(const float* __restrict__ x,
                                                 const float* __restrict__ g,
                                                 const float* __restrict__ bta,
                                                 float* __restrict__ out) {
    int row = blockIdx.x;
    int t = threadIdx.x;
    float v = x[(size_t)row * DIM + t];
    float s = v, s2 = v * v;
#pragma unroll
    for (int o = 16; o; o >>= 1) {
        s  += __shfl_xor_sync(0xffffffffu, s,  o);
        s2 += __shfl_xor_sync(0xffffffffu, s2, o);
    }
    __shared__ float sh[16];
    if ((t & 31) == 0) { sh[t >> 5] = s; sh[8 + (t >> 5)] = s2; }
    __syncthreads();
    float S = 0.f, S2 = 0.f;
#pragma unroll
    for (int w = 0; w < 8; w++) { S += sh[w]; S2 += sh[8 + w]; }
    float mu = S * (1.f / DIM);
    float var = S2 * (1.f / DIM) - mu * mu;
    float r = rsqrtf(var + 1e-5f);
    out[(size_t)row * DIM + t] = (v - mu) * r * g[t] + bta[t];
}

// ---------------- SGEMM 128x128x8, 256 threads, 8x8 microtile ----------------
// C[M,N] = A[M,K] @ W[K,N] + bias ; EPI: 0=bias, 1=bias+gelu, 2=bias+residual(in C)
__device__ __forceinline__ float gelu_exact(float x) {
    return 0.5f * x * (1.0f + erff(x * 0.70710678118654752f));
}

template<int EPI>
__global__ __launch_bounds__(256) void gemm_kernel(const float* __restrict__ A,
                                                   const float* __restrict__ W,
                                                   const float* __restrict__ bias,
                                                   float* __restrict__ C,
                                                   int M, int N, int K) {
    __shared__ float As[8][128];
    __shared__ float Bs[8][128];
    int tid = threadIdx.x;
    int m0 = blockIdx.y * 128, n0 = blockIdx.x * 128;
    int tx = tid & 15, ty = tid >> 4;

    int arow = tid >> 1, acol = (tid & 1) * 4;
    int brow = tid >> 5, bcol = (tid & 31) * 4;

    float acc[8][8];
#pragma unroll
    for (int i = 0; i < 8; i++)
#pragma unroll
        for (int j = 0; j < 8; j++) acc[i][j] = 0.f;

    for (int k0 = 0; k0 < K; k0 += 8) {
        float4 a4 = *(const float4*)&A[(size_t)(m0 + arow) * K + k0 + acol];
        As[acol + 0][arow] = a4.x;
        As[acol + 1][arow] = a4.y;
        As[acol + 2][arow] = a4.z;
        As[acol + 3][arow] = a4.w;
        *(float4*)&Bs[brow][bcol] =
            *(const float4*)&W[(size_t)(k0 + brow) * N + n0 + bcol];
        __syncthreads();
#pragma unroll
        for (int kk = 0; kk < 8; kk++) {
            float a[8], b[8];
            *(float4*)(a)     = *(float4*)&As[kk][ty * 8];
            *(float4*)(a + 4) = *(float4*)&As[kk][ty * 8 + 4];
            *(float4*)(b)     = *(float4*)&Bs[kk][tx * 8];
            *(float4*)(b + 4) = *(float4*)&Bs[kk][tx * 8 + 4];
#pragma unroll
            for (int i = 0; i < 8; i++)
#pragma unroll
                for (int j = 0; j < 8; j++) acc[i][j] += a[i] * b[j];
        }
        __syncthreads();
    }

#pragma unroll
    for (int i = 0; i < 8; i++) {
        int m = m0 + ty * 8 + i;
#pragma unroll
        for (int j = 0; j < 8; j += 4) {
            int n = n0 + tx * 8 + j;
            float4 r;
            r.x = acc[i][j + 0] + bias[n + 0];
            r.y = acc[i][j + 1] + bias[n + 1];
            r.z = acc[i][j + 2] + bias[n + 2];
            r.w = acc[i][j + 3] + bias[n + 3];
            if (EPI == 1) {
                r.x = gelu_exact(r.x); r.y = gelu_exact(r.y);
                r.z = gelu_exact(r.z); r.w = gelu_exact(r.w);
            }
            float4* cp = (float4*)&C[(size_t)m * N + n];
            if (EPI == 2) {
                float4 old = *cp;
                r.x += old.x; r.y += old.y; r.z += old.z; r.w += old.w;
            }
            *cp = r;
        }
    }
}

// ---------------- fused attention (online softmax), 64-query tile ----------------
// grid: (N/64, H, 2*B). kvswap=1 => stream s queries attend to stream 1-s kv (cross-attn).
// bias0/bias1: per-stream [B,H,N,N] additive bias (nullptr for cross-attn).
__global__ __launch_bounds__(256) void attn_kernel(const float* __restrict__ Q,
                                                   const float* __restrict__ K,
                                                   const float* __restrict__ V,
                                                   const float* __restrict__ bias0,
                                                   const float* __restrict__ bias1,
                                                   float* __restrict__ O,
                                                   int kvswap) {
    __shared__ float Qs[64][36];
    __shared__ float Ks[64][36];
    __shared__ float Vs[64][36];
    __shared__ float Ss[64][65];
    __shared__ float mrow[64], lrow[64], frow[64];

    int t = threadIdx.x;
    int qbase = blockIdx.x * 64;
    int h = blockIdx.y;
    int z = blockIdx.z;
    int s = z >> 2, b = z & 3;

    const float* qptr = Q + (((size_t)(s * BB + b)) * NN + qbase) * DIM + h * HD;
    int ks = s ^ kvswap;
    const float* kptr = K + (((size_t)(ks * BB + b)) * NN) * DIM + h * HD;
    const float* vptr = V + (((size_t)(ks * BB + b)) * NN) * DIM + h * HD;
    const float* bias = kvswap ? nullptr : (s == 0 ? bias0 : bias1);
    const float* bptr = bias ? bias + (((size_t)(b * HH + h)) * NN + qbase) * NN : nullptr;

#pragma unroll
    for (int i = 0; i < 8; i++) {
        int idx = t + i * 256;
        int r = idx >> 5, c = idx & 31;
        Qs[r][c] = qptr[(size_t)r * DIM + c] * SCALE;
    }
    if (t < 64) { mrow[t] = -1e30f; lrow[t] = 0.f; }

    float acc[8];
#pragma unroll
    for (int j = 0; j < 8; j++) acc[j] = 0.f;

    int tx = t & 15, ty = t >> 4;      // S-compute mapping (4x4 per thread)
    int orow = t >> 2, oc0 = (t & 3) * 8; // PV mapping (1 row x 8 cols per thread)
    __syncthreads();

    for (int kc = 0; kc < 16; kc++) {
        int kb = kc * 64;
#pragma unroll
        for (int i = 0; i < 8; i++) {
            int idx = t + i * 256;
            int r = idx >> 5, c = idx & 31;
            Ks[r][c] = kptr[(size_t)(kb + r) * DIM + c];
            Vs[r][c] = vptr[(size_t)(kb + r) * DIM + c];
        }
        __syncthreads();

        // S tile: rows ty*4..+3, cols tx*4..+3
        int r0 = ty * 4, c0 = tx * 4;
        float sc[4][4];
#pragma unroll
        for (int i = 0; i < 4; i++)
#pragma unroll
            for (int j = 0; j < 4; j++) sc[i][j] = 0.f;
#pragma unroll
        for (int d = 0; d < 32; d++) {
            float q0 = Qs[r0][d], q1 = Qs[r0 + 1][d], q2 = Qs[r0 + 2][d], q3 = Qs[r0 + 3][d];
            float k0 = Ks[c0][d], k1 = Ks[c0 + 1][d], k2 = Ks[c0 + 2][d], k3 = Ks[c0 + 3][d];
            sc[0][0] += q0 * k0; sc[0][1] += q0 * k1; sc[0][2] += q0 * k2; sc[0][3] += q0 * k3;
            sc[1][0] += q1 * k0; sc[1][1] += q1 * k1; sc[1][2] += q1 * k2; sc[1][3] += q1 * k3;
            sc[2][0] += q2 * k0; sc[2][1] += q2 * k1; sc[2][2] += q2 * k2; sc[2][3] += q2 * k3;
            sc[3][0] += q3 * k0; sc[3][1] += q3 * k1; sc[3][2] += q3 * k2; sc[3][3] += q3 * k3;
        }
#pragma unroll
        for (int i = 0; i < 4; i++)
#pragma unroll
            for (int j = 0; j < 4; j++) {
                float v = sc[i][j];
                if (bptr) v += bptr[(size_t)(r0 + i) * NN + kb + c0 + j];
                Ss[r0 + i][c0 + j] = v;
            }
        __syncthreads();

        // online softmax row update
        if (t < 64) {
            float m = mrow[t];
            float cmax = -1e30f;
#pragma unroll 8
            for (int c = 0; c < 64; c++) cmax = fmaxf(cmax, Ss[t][c]);
            float nm = fmaxf(m, cmax);
            float f = __expf(m - nm);
            float sum = 0.f;
#pragma unroll 8
            for (int c = 0; c < 64; c++) {
                float p = __expf(Ss[t][c] - nm);
                Ss[t][c] = p;
                sum += p;
            }
            lrow[t] = lrow[t] * f + sum;
            mrow[t] = nm;
            frow[t] = f;
        }
        __syncthreads();

        // O accumulate: acc = acc*f + P @ V
        float f = frow[orow];
#pragma unroll
        for (int j = 0; j < 8; j++) acc[j] *= f;
#pragma unroll 8
        for (int k = 0; k < 64; k++) {
            float p = Ss[orow][k];
            float4 va = *(const float4*)&Vs[k][oc0];
            float4 vb = *(const float4*)&Vs[k][oc0 + 4];
            acc[0] += p * va.x; acc[1] += p * va.y; acc[2] += p * va.z; acc[3] += p * va.w;
            acc[4] += p * vb.x; acc[5] += p * vb.y; acc[6] += p * vb.z; acc[7] += p * vb.w;
        }
        __syncthreads();
    }

    float inv = 1.f / lrow[orow];
    float* optr = O + (((size_t)(s * BB + b)) * NN + qbase + orow) * DIM + h * HD + oc0;
#pragma unroll
    for (int j = 0; j < 8; j++) optr[j] = acc[j] * inv;
}

// ---------------- host orchestration ----------------
static void launch_gemm(int epi, const float* A, const float* W, const float* bias,
                        float* C, int M, int N, int K) {
    dim3 g(N / 128, M / 128);
    if (epi == 0)      gemm_kernel<0><<<g, 256>>>(A, W, bias, C, M, N, K);
    else if (epi == 1) gemm_kernel<1><<<g, 256>>>(A, W, bias, C, M, N, K);
    else               gemm_kernel<2><<<g, 256>>>(A, W, bias, C, M, N, K);
}

extern "C" void kernel_launch(void* const* d_in, const int* in_sizes, int n_in,
                              void* d_out, int out_size) {
    const float* src_feats = (const float*)d_in[0];
    const float* tgt_feats = (const float*)d_in[1];
    const float* src_bias  = (const float*)d_in[2];
    const float* tgt_bias  = (const float*)d_in[3];
    const float* sa_q_w = (const float*)d_in[4];  const float* sa_q_b = (const float*)d_in[5];
    const float* sa_k_w = (const float*)d_in[6];  const float* sa_k_b = (const float*)d_in[7];
    const float* sa_v_w = (const float*)d_in[8];  const float* sa_v_b = (const float*)d_in[9];
    const float* sa_o_w = (const float*)d_in[10]; const float* sa_o_b = (const float*)d_in[11];
    const float* ca_q_w = (const float*)d_in[12]; const float* ca_q_b = (const float*)d_in[13];
    const float* ca_k_w = (const float*)d_in[14]; const float* ca_k_b = (const float*)d_in[15];
    const float* ca_v_w = (const float*)d_in[16]; const float* ca_v_b = (const float*)d_in[17];
    const float* ca_o_w = (const float*)d_in[18]; const float* ca_o_b = (const float*)d_in[19];
    const float* ln_sa_g = (const float*)d_in[20]; const float* ln_sa_b = (const float*)d_in[21];
    const float* ln_ca_g = (const float*)d_in[22]; const float* ln_ca_b = (const float*)d_in[23];
    const float* ln_ff_g = (const float*)d_in[24]; const float* ln_ff_b = (const float*)d_in[25];
    const float* ffn_w1 = (const float*)d_in[26]; const float* ffn_b1 = (const float*)d_in[27];
    const float* ffn_w2 = (const float*)d_in[28]; const float* ffn_b2 = (const float*)d_in[29];

    float* res = (float*)d_out; // [2, B, N, DIM] : src then tgt

    void *p_xn, *p_q, *p_k, *p_v, *p_ao, *p_h;
    cudaGetSymbolAddress(&p_xn, g_xn);
    cudaGetSymbolAddress(&p_q,  g_q);
    cudaGetSymbolAddress(&p_k,  g_k);
    cudaGetSymbolAddress(&p_v,  g_v);
    cudaGetSymbolAddress(&p_ao, g_ao);
    cudaGetSymbolAddress(&p_h,  g_h);
    float* xn = (float*)p_xn;
    float* qb = (float*)p_q;
    float* kb = (float*)p_k;
    float* vb = (float*)p_v;
    float* ao = (float*)p_ao;
    float* hb = (float*)p_h;

    // res = feats
    copy_feats_kernel<<<STREAM_ELEMS / 4 / 256, 256>>>(
        (const float4*)src_feats, (const float4*)tgt_feats, (float4*)res);

    dim3 agrid(NN / 64, HH, 2 * BB);

    // ---- 1. geometric self-attention ----
    ln_kernel<<<MROWS, 256>>>(res, ln_sa_g, ln_sa_b, xn);
    launch_gemm(0, xn, sa_q_w, sa_q_b, qb, MROWS, DIM, DIM);
    launch_gemm(0, xn, sa_k_w, sa_k_b, kb, MROWS, DIM, DIM);
    launch_gemm(0, xn, sa_v_w, sa_v_b, vb, MROWS, DIM, DIM);
    attn_kernel<<<agrid, 256>>>(qb, kb, vb, src_bias, tgt_bias, ao, 0);
    launch_gemm(2, ao, sa_o_w, sa_o_b, res, MROWS, DIM, DIM);

    // ---- 2. cross-attention (q from own stream norm, kv from other) ----
    ln_kernel<<<MROWS, 256>>>(res, ln_ca_g, ln_ca_b, xn);
    launch_gemm(0, xn, ca_q_w, ca_q_b, qb, MROWS, DIM, DIM);
    launch_gemm(0, xn, ca_k_w, ca_k_b, kb, MROWS, DIM, DIM);
    launch_gemm(0, xn, ca_v_w, ca_v_b, vb, MROWS, DIM, DIM);
    attn_kernel<<<agrid, 256>>>(qb, kb, vb, nullptr, nullptr, ao, 1);
    launch_gemm(2, ao, ca_o_w, ca_o_b, res, MROWS, DIM, DIM);

    // ---- 3. FFN ----
    ln_kernel<<<MROWS, 256>>>(res, ln_ff_g, ln_ff_b, xn);
    launch_gemm(1, xn, ffn_w1, ffn_b1, hb, MROWS, FFN_DIM, DIM);
    launch_gemm(2, hb, ffn_w2, ffn_b2, res, MROWS, DIM, FFN_DIM);
}

// round 2
// speedup vs baseline: 1.2445x; 1.2445x over previous
#include <cuda_runtime.h>
#include <math.h>
#include <stdint.h>

#define BB 4
#define NN 1024
#define DIM 256
#define HH 8
#define HD 32
#define FFN_DIM 1024
#define MROWS (2 * BB * NN)          // 8192 combined rows (src+tgt)
#define STREAM_ELEMS (BB * NN * DIM) // 1048576
#define SCALE 0.17677669529663687f   // 1/sqrt(32)

// ---------------- scratch (static device memory; no allocation) ----------------
__device__ float g_xn[MROWS * DIM];
__device__ float g_q [MROWS * DIM];
__device__ float g_k [MROWS * DIM];
__device__ float g_v [MROWS * DIM];
__device__ float g_ao[MROWS * DIM];
__device__ float g_h [MROWS * FFN_DIM];

// ---------------- residual init: res = feats ----------------
__global__ void copy_feats_kernel(const float4* __restrict__ a,
                                  const float4* __restrict__ b,
                                  float4* __restrict__ out) {
    int i = blockIdx.x * blockDim.x + threadIdx.x;
    out[i] = a[i];
    out[i + STREAM_ELEMS / 4] = b[i];
}

// ---------------- LayerNorm: one block (256 thr) per row ----------------
__global__ __launch_bounds__(256) void ln_kernel(const float* __restrict__ x,
                                                 const float* __restrict__ g,
                                                 const float* __restrict__ bta,
                                                 float* __restrict__ out) {
    int row = blockIdx.x;
    int t = threadIdx.x;
    float v = x[(size_t)row * DIM + t];
    float s = v, s2 = v * v;
#pragma unroll
    for (int o = 16; o; o >>= 1) {
        s  += __shfl_xor_sync(0xffffffffu, s,  o);
        s2 += __shfl_xor_sync(0xffffffffu, s2, o);
    }
    __shared__ float sh[16];
    if ((t & 31) == 0) { sh[t >> 5] = s; sh[8 + (t >> 5)] = s2; }
    __syncthreads();
    float S = 0.f, S2 = 0.f;
#pragma unroll
    for (int w = 0; w < 8; w++) { S += sh[w]; S2 += sh[8 + w]; }
    float mu = S * (1.f / DIM);
    float var = S2 * (1.f / DIM) - mu * mu;
    float r = rsqrtf(var + 1e-5f);
    out[(size_t)row * DIM + t] = (v - mu) * r * g[t] + bta[t];
}

// ---------------- tf32 tensor-core GEMM ----------------
// C[M,N] = A[M,K] @ W[K,N] + bias ; EPI: 0=bias, 1=bias+gelu, 2=bias+residual(in C)
// Block tile 128x128, Kstage 32, 8 warps (2x4), warp tile 64x32 of m16n8k8 mma.

__device__ __forceinline__ float gelu_exact(float x) {
    return 0.5f * x * (1.0f + erff(x * 0.70710678118654752f));
}

__device__ __forceinline__ void cp16(void* dst, const void* src) {
    uint32_t s = (uint32_t)__cvta_generic_to_shared(dst);
    asm volatile("cp.async.cg.shared.global [%0], [%1], 16;" :: "r"(s), "l"(src));
}

__device__ __forceinline__ void mma_tf32(float* d, const uint32_t* a, const uint32_t* b) {
    asm volatile("mma.sync.aligned.m16n8k8.row.col.f32.tf32.tf32.f32 "
        "{%0,%1,%2,%3}, {%4,%5,%6,%7}, {%8,%9}, {%0,%1,%2,%3};"
        : "+f"(d[0]), "+f"(d[1]), "+f"(d[2]), "+f"(d[3])
        : "r"(a[0]), "r"(a[1]), "r"(a[2]), "r"(a[3]), "r"(b[0]), "r"(b[1]));
}

#define AS_STRIDE 36    // bank = (36*m + c) % 32 = 4m + c : conflict-free frag loads
#define BS_STRIDE 136   // 136 % 32 = 8 : 4 k-rows x 8 n-cols cover all banks
#define GEMM_SMEM ((2 * 128 * AS_STRIDE + 2 * 32 * BS_STRIDE) * 4)

template<int EPI>
__global__ __launch_bounds__(256) void gemm_tf32(const float* __restrict__ A,
                                                 const float* __restrict__ W,
                                                 const float* __restrict__ bias,
                                                 float* __restrict__ C,
                                                 int M, int N, int K) {
    extern __shared__ float smem[];
    float (*As)[128][AS_STRIDE] = (float (*)[128][AS_STRIDE])smem;
    float (*Bs)[32][BS_STRIDE]  = (float (*)[32][BS_STRIDE])(smem + 2 * 128 * AS_STRIDE);

    int tid = threadIdx.x;
    int lane = tid & 31, wid = tid >> 5;
    int wm = wid & 1, wn = wid >> 1;  // warps: 2 (M) x 4 (N)
    int m0 = blockIdx.y * 128, n0 = blockIdx.x * 128;

    // gmem->smem mappings
    int a_r = tid >> 3, a_c = (tid & 7) * 4;          // + i*32 rows
    int b_r = tid >> 5, b_c = (tid & 31) * 4;         // + i*8 rows

    float acc[4][4][4];
#pragma unroll
    for (int mt = 0; mt < 4; mt++)
#pragma unroll
        for (int nt = 0; nt < 4; nt++)
#pragma unroll
            for (int r = 0; r < 4; r++) acc[mt][nt][r] = 0.f;

    int nstages = K / 32;

    // prologue: load stage 0 into buf 0
#pragma unroll
    for (int i = 0; i < 4; i++)
        cp16(&As[0][a_r + i * 32][a_c], &A[(size_t)(m0 + a_r + i * 32) * K + a_c]);
#pragma unroll
    for (int i = 0; i < 4; i++)
        cp16(&Bs[0][b_r + i * 8][b_c], &W[(size_t)(b_r + i * 8) * N + n0 + b_c]);
    asm volatile("cp.async.commit_group;");

    int buf = 0;
    for (int s = 0; s < nstages; s++) {
        if (s + 1 < nstages) {
            int k0 = (s + 1) * 32;
#pragma unroll
            for (int i = 0; i < 4; i++)
                cp16(&As[buf ^ 1][a_r + i * 32][a_c],
                     &A[(size_t)(m0 + a_r + i * 32) * K + k0 + a_c]);
#pragma unroll
            for (int i = 0; i < 4; i++)
                cp16(&Bs[buf ^ 1][b_r + i * 8][b_c],
                     &W[(size_t)(k0 + b_r + i * 8) * N + n0 + b_c]);
            asm volatile("cp.async.commit_group;");
            asm volatile("cp.async.wait_group 1;");
        } else {
            asm volatile("cp.async.wait_group 0;");
        }
        __syncthreads();

        // compute from As[buf], Bs[buf]: 4 k-steps of 8
        int ar0 = wm * 64 + (lane >> 2);
        int bc0 = wn * 32 + (lane >> 2);
#pragma unroll
        for (int kk = 0; kk < 4; kk++) {
            int ac = kk * 8 + (lane & 3);
            int br = kk * 8 + (lane & 3);
            uint32_t aF[4][4], bF[4][2];
#pragma unroll
            for (int mt = 0; mt < 4; mt++) {
                aF[mt][0] = __float_as_uint(As[buf][ar0 + mt * 16][ac]);
                aF[mt][1] = __float_as_uint(As[buf][ar0 + mt * 16 + 8][ac]);
                aF[mt][2] = __float_as_uint(As[buf][ar0 + mt * 16][ac + 4]);
                aF[mt][3] = __float_as_uint(As[buf][ar0 + mt * 16 + 8][ac + 4]);
            }
#pragma unroll
            for (int nt = 0; nt < 4; nt++) {
                bF[nt][0] = __float_as_uint(Bs[buf][br][bc0 + nt * 8]);
                bF[nt][1] = __float_as_uint(Bs[buf][br + 4][bc0 + nt * 8]);
            }
#pragma unroll
            for (int mt = 0; mt < 4; mt++)
#pragma unroll
                for (int nt = 0; nt < 4; nt++)
                    mma_tf32(acc[mt][nt], aF[mt], bF[nt]);
        }
        __syncthreads();
        buf ^= 1;
    }

    // epilogue
#pragma unroll
    for (int mt = 0; mt < 4; mt++) {
        int mA = m0 + wm * 64 + mt * 16 + (lane >> 2);
#pragma unroll
        for (int nt = 0; nt < 4; nt++) {
            int n = n0 + wn * 32 + nt * 8 + 2 * (lane & 3);
            float bx = bias[n], by = bias[n + 1];
#pragma unroll
            for (int h = 0; h < 2; h++) {
                int m = mA + h * 8;
                float vx = acc[mt][nt][2 * h + 0] + bx;
                float vy = acc[mt][nt][2 * h + 1] + by;
                if (EPI == 1) { vx = gelu_exact(vx); vy = gelu_exact(vy); }
                float2* cp = (float2*)&C[(size_t)m * N + n];
                if (EPI == 2) {
                    float2 old = *cp;
                    vx += old.x; vy += old.y;
                }
                *cp = make_float2(vx, vy);
            }
        }
    }
}

// ---------------- fused attention (online softmax), 64-query tile ----------------
__global__ __launch_bounds__(256) void attn_kernel(const float* __restrict__ Q,
                                                   const float* __restrict__ K,
                                                   const float* __restrict__ V,
                                                   const float* __restrict__ bias0,
                                                   const float* __restrict__ bias1,
                                                   float* __restrict__ O,
                                                   int kvswap) {
    __shared__ float Qs[64][36];
    __shared__ float Ks[64][36];
    __shared__ float Vs[64][36];
    __shared__ float Ss[64][65];
    __shared__ float mrow[64], lrow[64], frow[64];

    int t = threadIdx.x;
    int qbase = blockIdx.x * 64;
    int h = blockIdx.y;
    int z = blockIdx.z;
    int s = z >> 2, b = z & 3;

    const float* qptr = Q + (((size_t)(s * BB + b)) * NN + qbase) * DIM + h * HD;
    int ks = s ^ kvswap;
    const float* kptr = K + (((size_t)(ks * BB + b)) * NN) * DIM + h * HD;
    const float* vptr = V + (((size_t)(ks * BB + b)) * NN) * DIM + h * HD;
    const float* bias = kvswap ? nullptr : (s == 0 ? bias0 : bias1);
    const float* bptr = bias ? bias + (((size_t)(b * HH + h)) * NN + qbase) * NN : nullptr;

#pragma unroll
    for (int i = 0; i < 8; i++) {
        int idx = t + i * 256;
        int r = idx >> 5, c = idx & 31;
        Qs[r][c] = qptr[(size_t)r * DIM + c] * SCALE;
    }
    if (t < 64) { mrow[t] = -1e30f; lrow[t] = 0.f; }

    float acc[8];
#pragma unroll
    for (int j = 0; j < 8; j++) acc[j] = 0.f;

    int tx = t & 15, ty = t >> 4;
    int orow = t >> 2, oc0 = (t & 3) * 8;
    __syncthreads();

    for (int kc = 0; kc < 16; kc++) {
        int kb = kc * 64;
#pragma unroll
        for (int i = 0; i < 8; i++) {
            int idx = t + i * 256;
            int r = idx >> 5, c = idx & 31;
            Ks[r][c] = kptr[(size_t)(kb + r) * DIM + c];
            Vs[r][c] = vptr[(size_t)(kb + r) * DIM + c];
        }
        __syncthreads();

        int r0 = ty * 4, c0 = tx * 4;
        float sc[4][4];
#pragma unroll
        for (int i = 0; i < 4; i++)
#pragma unroll
            for (int j = 0; j < 4; j++) sc[i][j] = 0.f;
#pragma unroll
        for (int d = 0; d < 32; d++) {
            float q0 = Qs[r0][d], q1 = Qs[r0 + 1][d], q2 = Qs[r0 + 2][d], q3 = Qs[r0 + 3][d];
            float k0 = Ks[c0][d], k1 = Ks[c0 + 1][d], k2 = Ks[c0 + 2][d], k3 = Ks[c0 + 3][d];
            sc[0][0] += q0 * k0; sc[0][1] += q0 * k1; sc[0][2] += q0 * k2; sc[0][3] += q0 * k3;
            sc[1][0] += q1 * k0; sc[1][1] += q1 * k1; sc[1][2] += q1 * k2; sc[1][3] += q1 * k3;
            sc[2][0] += q2 * k0; sc[2][1] += q2 * k1; sc[2][2] += q2 * k2; sc[2][3] += q2 * k3;
            sc[3][0] += q3 * k0; sc[3][1] += q3 * k1; sc[3][2] += q3 * k2; sc[3][3] += q3 * k3;
        }
#pragma unroll
        for (int i = 0; i < 4; i++)
#pragma unroll
            for (int j = 0; j < 4; j++) {
                float v = sc[i][j];
                if (bptr) v += bptr[(size_t)(r0 + i) * NN + kb + c0 + j];
                Ss[r0 + i][c0 + j] = v;
            }
        __syncthreads();

        if (t < 64) {
            float m = mrow[t];
            float cmax = -1e30f;
#pragma unroll 8
            for (int c = 0; c < 64; c++) cmax = fmaxf(cmax, Ss[t][c]);
            float nm = fmaxf(m, cmax);
            float f = __expf(m - nm);
            float sum = 0.f;
#pragma unroll 8
            for (int c = 0; c < 64; c++) {
                float p = __expf(Ss[t][c] - nm);
                Ss[t][c] = p;
                sum += p;
            }
            lrow[t] = lrow[t] * f + sum;
            mrow[t] = nm;
            frow[t] = f;
        }
        __syncthreads();

        float f = frow[orow];
#pragma unroll
        for (int j = 0; j < 8; j++) acc[j] *= f;
#pragma unroll 8
        for (int k = 0; k < 64; k++) {
            float p = Ss[orow][k];
            float4 va = *(const float4*)&Vs[k][oc0];
            float4 vb = *(const float4*)&Vs[k][oc0 + 4];
            acc[0] += p * va.x; acc[1] += p * va.y; acc[2] += p * va.z; acc[3] += p * va.w;
            acc[4] += p * vb.x; acc[5] += p * vb.y; acc[6] += p * vb.z; acc[7] += p * vb.w;
        }
        __syncthreads();
    }

    float inv = 1.f / lrow[orow];
    float* optr = O + (((size_t)(s * BB + b)) * NN + qbase + orow) * DIM + h * HD + oc0;
#pragma unroll
    for (int j = 0; j < 8; j++) optr[j] = acc[j] * inv;
}

// ---------------- host orchestration ----------------
static void launch_gemm(int epi, const float* A, const float* W, const float* bias,
                        float* C, int M, int N, int K) {
    dim3 g(N / 128, M / 128);
    if (epi == 0)      gemm_tf32<0><<<g, 256, GEMM_SMEM>>>(A, W, bias, C, M, N, K);
    else if (epi == 1) gemm_tf32<1><<<g, 256, GEMM_SMEM>>>(A, W, bias, C, M, N, K);
    else               gemm_tf32<2><<<g, 256, GEMM_SMEM>>>(A, W, bias, C, M, N, K);
}

extern "C" void kernel_launch(void* const* d_in, const int* in_sizes, int n_in,
                              void* d_out, int out_size) {
    const float* src_feats = (const float*)d_in[0];
    const float* tgt_feats = (const float*)d_in[1];
    const float* src_bias  = (const float*)d_in[2];
    const float* tgt_bias  = (const float*)d_in[3];
    const float* sa_q_w = (const float*)d_in[4];  const float* sa_q_b = (const float*)d_in[5];
    const float* sa_k_w = (const float*)d_in[6];  const float* sa_k_b = (const float*)d_in[7];
    const float* sa_v_w = (const float*)d_in[8];  const float* sa_v_b = (const float*)d_in[9];
    const float* sa_o_w = (const float*)d_in[10]; const float* sa_o_b = (const float*)d_in[11];
    const float* ca_q_w = (const float*)d_in[12]; const float* ca_q_b = (const float*)d_in[13];
    const float* ca_k_w = (const float*)d_in[14]; const float* ca_k_b = (const float*)d_in[15];
    const float* ca_v_w = (const float*)d_in[16]; const float* ca_v_b = (const float*)d_in[17];
    const float* ca_o_w = (const float*)d_in[18]; const float* ca_o_b = (const float*)d_in[19];
    const float* ln_sa_g = (const float*)d_in[20]; const float* ln_sa_b = (const float*)d_in[21];
    const float* ln_ca_g = (const float*)d_in[22]; const float* ln_ca_b = (const float*)d_in[23];
    const float* ln_ff_g = (const float*)d_in[24]; const float* ln_ff_b = (const float*)d_in[25];
    const float* ffn_w1 = (const float*)d_in[26]; const float* ffn_b1 = (const float*)d_in[27];
    const float* ffn_w2 = (const float*)d_in[28]; const float* ffn_b2 = (const float*)d_in[29];

    float* res = (float*)d_out; // [2, B, N, DIM] : src then tgt

    // raise dynamic smem limit (idempotent, called every launch - no static guards)
    cudaFuncSetAttribute(gemm_tf32<0>, cudaFuncAttributeMaxDynamicSharedMemorySize, GEMM_SMEM);
    cudaFuncSetAttribute(gemm_tf32<1>, cudaFuncAttributeMaxDynamicSharedMemorySize, GEMM_SMEM);
    cudaFuncSetAttribute(gemm_tf32<2>, cudaFuncAttributeMaxDynamicSharedMemorySize, GEMM_SMEM);

    void *p_xn, *p_q, *p_k, *p_v, *p_ao, *p_h;
    cudaGetSymbolAddress(&p_xn, g_xn);
    cudaGetSymbolAddress(&p_q,  g_q);
    cudaGetSymbolAddress(&p_k,  g_k);
    cudaGetSymbolAddress(&p_v,  g_v);
    cudaGetSymbolAddress(&p_ao, g_ao);
    cudaGetSymbolAddress(&p_h,  g_h);
    float* xn = (float*)p_xn;
    float* qb = (float*)p_q;
    float* kb = (float*)p_k;
    float* vb = (float*)p_v;
    float* ao = (float*)p_ao;
    float* hb = (float*)p_h;

    // res = feats
    copy_feats_kernel<<<STREAM_ELEMS / 4 / 256, 256>>>(
        (const float4*)src_feats, (const float4*)tgt_feats, (float4*)res);

    dim3 agrid(NN / 64, HH, 2 * BB);

    // ---- 1. geometric self-attention ----
    ln_kernel<<<MROWS, 256>>>(res, ln_sa_g, ln_sa_b, xn);
    launch_gemm(0, xn, sa_q_w, sa_q_b, qb, MROWS, DIM, DIM);
    launch_gemm(0, xn, sa_k_w, sa_k_b, kb, MROWS, DIM, DIM);
    launch_gemm(0, xn, sa_v_w, sa_v_b, vb, MROWS, DIM, DIM);
    attn_kernel<<<agrid, 256>>>(qb, kb, vb, src_bias, tgt_bias, ao, 0);
    launch_gemm(2, ao, sa_o_w, sa_o_b, res, MROWS, DIM, DIM);

    // ---- 2. cross-attention ----
    ln_kernel<<<MROWS, 256>>>(res, ln_ca_g, ln_ca_b, xn);
    launch_gemm(0, xn, ca_q_w, ca_q_b, qb, MROWS, DIM, DIM);
    launch_gemm(0, xn, ca_k_w, ca_k_b, kb, MROWS, DIM, DIM);
    launch_gemm(0, xn, ca_v_w, ca_v_b, vb, MROWS, DIM, DIM);
    attn_kernel<<<agrid, 256>>>(qb, kb, vb, nullptr, nullptr, ao, 1);
    launch_gemm(2, ao, ca_o_w, ca_o_b, res, MROWS, DIM, DIM);

    // ---- 3. FFN ----
    ln_kernel<<<MROWS, 256>>>(res, ln_ff_g, ln_ff_b, xn);
    launch_gemm(1, xn, ffn_w1, ffn_b1, hb, MROWS, FFN_DIM, DIM);
    launch_gemm(2, hb, ffn_w2, ffn_b2, res, MROWS, DIM, FFN_DIM);
}

// round 5
// speedup vs baseline: 3.8784x; 3.1166x over previous
#include <cuda_runtime.h>
#include <math.h>
#include <stdint.h>

#define BB 4
#define NN 1024
#define DIM 256
#define HH 8
#define HD 32
#define FFN_DIM 1024
#define MROWS (2 * BB * NN)          // 8192 combined rows (src+tgt)
#define STREAM_ELEMS (BB * NN * DIM) // 1048576
#define SCALE 0.17677669529663687f   // 1/sqrt(32)

// ---------------- scratch (static device memory; no allocation) ----------------
__device__ float g_xn[MROWS * DIM];
__device__ float g_q [MROWS * DIM];
__device__ float g_k [MROWS * DIM];
__device__ float g_v [MROWS * DIM];
__device__ float g_ao[MROWS * DIM];
__device__ float g_h [MROWS * FFN_DIM];

// ---------------- residual init: res = feats ----------------
__global__ void copy_feats_kernel(const float4* __restrict__ a,
                                  const float4* __restrict__ b,
                                  float4* __restrict__ out) {
    int i = blockIdx.x * blockDim.x + threadIdx.x;
    out[i] = a[i];
    out[i + STREAM_ELEMS / 4] = b[i];
}

// ---------------- LayerNorm: one block (256 thr) per row ----------------
__global__ __launch_bounds__(256) void ln_kernel(const float* __restrict__ x,
                                                 const float* __restrict__ g,
                                                 const float* __restrict__ bta,
                                                 float* __restrict__ out) {
    int row = blockIdx.x;
    int t = threadIdx.x;
    float v = x[(size_t)row * DIM + t];
    float s = v, s2 = v * v;
#pragma unroll
    for (int o = 16; o; o >>= 1) {
        s  += __shfl_xor_sync(0xffffffffu, s,  o);
        s2 += __shfl_xor_sync(0xffffffffu, s2, o);
    }
    __shared__ float sh[16];
    if ((t & 31) == 0) { sh[t >> 5] = s; sh[8 + (t >> 5)] = s2; }
    __syncthreads();
    float S = 0.f, S2 = 0.f;
#pragma unroll
    for (int w = 0; w < 8; w++) { S += sh[w]; S2 += sh[8 + w]; }
    float mu = S * (1.f / DIM);
    float var = S2 * (1.f / DIM) - mu * mu;
    float r = rsqrtf(var + 1e-5f);
    out[(size_t)row * DIM + t] = (v - mu) * r * g[t] + bta[t];
}

// ---------------- common PTX helpers ----------------
__device__ __forceinline__ float gelu_exact(float x) {
    return 0.5f * x * (1.0f + erff(x * 0.70710678118654752f));
}

__device__ __forceinline__ void cp16(void* dst, const void* src) {
    uint32_t s = (uint32_t)__cvta_generic_to_shared(dst);
    asm volatile("cp.async.cg.shared.global [%0], [%1], 16;" :: "r"(s), "l"(src));
}

__device__ __forceinline__ void mma_tf32(float* d, const uint32_t* a, const uint32_t* b) {
    asm volatile("mma.sync.aligned.m16n8k8.row.col.f32.tf32.tf32.f32 "
        "{%0,%1,%2,%3}, {%4,%5,%6,%7}, {%8,%9}, {%0,%1,%2,%3};"
        : "+f"(d[0]), "+f"(d[1]), "+f"(d[2]), "+f"(d[3])
        : "r"(a[0]), "r"(a[1]), "r"(a[2]), "r"(a[3]), "r"(b[0]), "r"(b[1]));
}

// ---------------- tf32 tensor-core GEMM ----------------
#define AS_STRIDE 36    // bank = 4m + c : conflict-free frag loads
#define BS_STRIDE 136   // 136 % 32 = 8
#define GEMM_SMEM ((2 * 128 * AS_STRIDE + 2 * 32 * BS_STRIDE) * 4)

template<int EPI>
__global__ __launch_bounds__(256) void gemm_tf32(const float* __restrict__ A,
                                                 const float* __restrict__ W,
                                                 const float* __restrict__ bias,
                                                 float* __restrict__ C,
                                                 int M, int N, int K) {
    extern __shared__ float smem[];
    float (*As)[128][AS_STRIDE] = (float (*)[128][AS_STRIDE])smem;
    float (*Bs)[32][BS_STRIDE]  = (float (*)[32][BS_STRIDE])(smem + 2 * 128 * AS_STRIDE);

    int tid = threadIdx.x;
    int lane = tid & 31, wid = tid >> 5;
    int wm = wid & 1, wn = wid >> 1;
    int m0 = blockIdx.y * 128, n0 = blockIdx.x * 128;

    int a_r = tid >> 3, a_c = (tid & 7) * 4;
    int b_r = tid >> 5, b_c = (tid & 31) * 4;

    float acc[4][4][4];
#pragma unroll
    for (int mt = 0; mt < 4; mt++)
#pragma unroll
        for (int nt = 0; nt < 4; nt++)
#pragma unroll
            for (int r = 0; r < 4; r++) acc[mt][nt][r] = 0.f;

    int nstages = K / 32;

#pragma unroll
    for (int i = 0; i < 4; i++)
        cp16(&As[0][a_r + i * 32][a_c], &A[(size_t)(m0 + a_r + i * 32) * K + a_c]);
#pragma unroll
    for (int i = 0; i < 4; i++)
        cp16(&Bs[0][b_r + i * 8][b_c], &W[(size_t)(b_r + i * 8) * N + n0 + b_c]);
    asm volatile("cp.async.commit_group;");

    int buf = 0;
    for (int s = 0; s < nstages; s++) {
        if (s + 1 < nstages) {
            int k0 = (s + 1) * 32;
#pragma unroll
            for (int i = 0; i < 4; i++)
                cp16(&As[buf ^ 1][a_r + i * 32][a_c],
                     &A[(size_t)(m0 + a_r + i * 32) * K + k0 + a_c]);
#pragma unroll
            for (int i = 0; i < 4; i++)
                cp16(&Bs[buf ^ 1][b_r + i * 8][b_c],
                     &W[(size_t)(k0 + b_r + i * 8) * N + n0 + b_c]);
            asm volatile("cp.async.commit_group;");
            asm volatile("cp.async.wait_group 1;");
        } else {
            asm volatile("cp.async.wait_group 0;");
        }
        __syncthreads();

        int ar0 = wm * 64 + (lane >> 2);
        int bc0 = wn * 32 + (lane >> 2);
#pragma unroll
        for (int kk = 0; kk < 4; kk++) {
            int ac = kk * 8 + (lane & 3);
            int br = kk * 8 + (lane & 3);
            uint32_t aF[4][4], bF[4][2];
#pragma unroll
            for (int mt = 0; mt < 4; mt++) {
                aF[mt][0] = __float_as_uint(As[buf][ar0 + mt * 16][ac]);
                aF[mt][1] = __float_as_uint(As[buf][ar0 + mt * 16 + 8][ac]);
                aF[mt][2] = __float_as_uint(As[buf][ar0 + mt * 16][ac + 4]);
                aF[mt][3] = __float_as_uint(As[buf][ar0 + mt * 16 + 8][ac + 4]);
            }
#pragma unroll
            for (int nt = 0; nt < 4; nt++) {
                bF[nt][0] = __float_as_uint(Bs[buf][br][bc0 + nt * 8]);
                bF[nt][1] = __float_as_uint(Bs[buf][br + 4][bc0 + nt * 8]);
            }
#pragma unroll
            for (int mt = 0; mt < 4; mt++)
#pragma unroll
                for (int nt = 0; nt < 4; nt++)
                    mma_tf32(acc[mt][nt], aF[mt], bF[nt]);
        }
        __syncthreads();
        buf ^= 1;
    }

#pragma unroll
    for (int mt = 0; mt < 4; mt++) {
        int mA = m0 + wm * 64 + mt * 16 + (lane >> 2);
#pragma unroll
        for (int nt = 0; nt < 4; nt++) {
            int n = n0 + wn * 32 + nt * 8 + 2 * (lane & 3);
            float bx = bias[n], by = bias[n + 1];
#pragma unroll
            for (int h = 0; h < 2; h++) {
                int m = mA + h * 8;
                float vx = acc[mt][nt][2 * h + 0] + bx;
                float vy = acc[mt][nt][2 * h + 1] + by;
                if (EPI == 1) { vx = gelu_exact(vx); vy = gelu_exact(vy); }
                float2* cp = (float2*)&C[(size_t)m * N + n];
                if (EPI == 2) {
                    float2 old = *cp;
                    vx += old.x; vy += old.y;
                }
                *cp = make_float2(vx, vy);
            }
        }
    }
}

// ---------------- tf32 tensor-core flash attention ----------------
// 64-query tile, 64-key chunks, 4 warps. Warp w owns S rows [16w,16w+16).
// smem (floats): Qs[64][36] @0, Ks[2][64][36] @2304, Vs[2][64][40] @6912, Ss[64][68] @12032
#define ATTN_SMEM (16384 * 4)

__global__ __launch_bounds__(128) void attn_mma(const float* __restrict__ Q,
                                                const float* __restrict__ K,
                                                const float* __restrict__ V,
                                                const float* __restrict__ bias0,
                                                const float* __restrict__ bias1,
                                                float* __restrict__ O,
                                                int kvswap) {
    extern __shared__ float sm[];
    float (*Qs)[36]     = (float (*)[36])sm;
    float (*Ks)[64][36] = (float (*)[64][36])(sm + 2304);
    float (*Vs)[64][40] = (float (*)[64][40])(sm + 6912);
    float (*Ss)[68]     = (float (*)[68])(sm + 12032);

    int t = threadIdx.x;
    int lane = t & 31, w = t >> 5;
    int gr = lane >> 2, gc = lane & 3;
    int qbase = blockIdx.x * 64;
    int h = blockIdx.y;
    int z = blockIdx.z;
    int s = z >> 2, b = z & 3;

    const float* qptr = Q + (((size_t)(s * BB + b)) * NN + qbase) * DIM + h * HD;
    int ks = s ^ kvswap;
    const float* kptr = K + ((size_t)(ks * BB + b)) * NN * DIM + h * HD;
    const float* vptr = V + ((size_t)(ks * BB + b)) * NN * DIM + h * HD;
    const float* bias = kvswap ? nullptr : (s == 0 ? bias0 : bias1);
    const float* bptr = bias ? bias + (((size_t)(b * HH + h)) * NN + qbase) * NN : nullptr;

    // load Q (pre-scaled)
#pragma unroll
    for (int i = 0; i < 4; i++) {
        int lin = t + i * 128;
        int r = lin >> 3, c = (lin & 7) * 4;
        float4 v4 = *(const float4*)&qptr[(size_t)r * DIM + c];
        Qs[r][c]     = v4.x * SCALE;
        Qs[r][c + 1] = v4.y * SCALE;
        Qs[r][c + 2] = v4.z * SCALE;
        Qs[r][c + 3] = v4.w * SCALE;
    }

    float m0 = -1e30f, m1 = -1e30f, l0 = 0.f, l1 = 0.f;
    float oa[4][4];
#pragma unroll
    for (int nt = 0; nt < 4; nt++)
#pragma unroll
        for (int r = 0; r < 4; r++) oa[nt][r] = 0.f;

    // prologue: chunk 0 -> buf 0
#pragma unroll
    for (int i = 0; i < 4; i++) {
        int lin = t + i * 128;
        int r = lin >> 3, c = (lin & 7) * 4;
        cp16(&Ks[0][r][c], &kptr[(size_t)r * DIM + c]);
        cp16(&Vs[0][r][c], &vptr[(size_t)r * DIM + c]);
    }
    asm volatile("cp.async.commit_group;");

    int buf = 0;
    for (int kc = 0; kc < 16; kc++) {
        int kb = kc * 64;
        if (kc + 1 < 16) {
            int kb2 = (kc + 1) * 64;
#pragma unroll
            for (int i = 0; i < 4; i++) {
                int lin = t + i * 128;
                int r = lin >> 3, c = (lin & 7) * 4;
                cp16(&Ks[buf ^ 1][r][c], &kptr[(size_t)(kb2 + r) * DIM + c]);
                cp16(&Vs[buf ^ 1][r][c], &vptr[(size_t)(kb2 + r) * DIM + c]);
            }
            asm volatile("cp.async.commit_group;");
            asm volatile("cp.async.wait_group 1;");
        } else {
            asm volatile("cp.async.wait_group 0;");
        }
        __syncthreads();

        // ---- S = Q @ K^T (+bias) ----
        float sacc[8][4];
#pragma unroll
        for (int nt = 0; nt < 8; nt++)
#pragma unroll
            for (int r = 0; r < 4; r++) sacc[nt][r] = 0.f;

#pragma unroll
        for (int kk = 0; kk < 4; kk++) {
            uint32_t aF[4];
            aF[0] = __float_as_uint(Qs[16 * w + gr][kk * 8 + gc]);
            aF[1] = __float_as_uint(Qs[16 * w + gr + 8][kk * 8 + gc]);
            aF[2] = __float_as_uint(Qs[16 * w + gr][kk * 8 + gc + 4]);
            aF[3] = __float_as_uint(Qs[16 * w + gr + 8][kk * 8 + gc + 4]);
#pragma unroll
            for (int nt = 0; nt < 8; nt++) {
                uint32_t bF[2];
                bF[0] = __float_as_uint(Ks[buf][nt * 8 + gr][kk * 8 + gc]);
                bF[1] = __float_as_uint(Ks[buf][nt * 8 + gr][kk * 8 + gc + 4]);
                mma_tf32(sacc[nt], aF, bF);
            }
        }
        if (bptr) {
#pragma unroll
            for (int nt = 0; nt < 8; nt++) {
                int col = kb + nt * 8 + 2 * gc;
                float2 u0 = *(const float2*)&bptr[(size_t)(16 * w + gr) * NN + col];
                float2 u1 = *(const float2*)&bptr[(size_t)(16 * w + gr + 8) * NN + col];
                sacc[nt][0] += u0.x; sacc[nt][1] += u0.y;
                sacc[nt][2] += u1.x; sacc[nt][3] += u1.y;
            }
        }

        // ---- online softmax (rows gr and gr+8, quad-local) ----
        float cm0 = -1e30f, cm1 = -1e30f;
#pragma unroll
        for (int nt = 0; nt < 8; nt++) {
            cm0 = fmaxf(cm0, fmaxf(sacc[nt][0], sacc[nt][1]));
            cm1 = fmaxf(cm1, fmaxf(sacc[nt][2], sacc[nt][3]));
        }
        cm0 = fmaxf(cm0, __shfl_xor_sync(0xffffffffu, cm0, 1));
        cm0 = fmaxf(cm0, __shfl_xor_sync(0xffffffffu, cm0, 2));
        cm1 = fmaxf(cm1, __shfl_xor_sync(0xffffffffu, cm1, 1));
        cm1 = fmaxf(cm1, __shfl_xor_sync(0xffffffffu, cm1, 2));
        float nm0 = fmaxf(m0, cm0), nm1 = fmaxf(m1, cm1);
        float f0 = __expf(m0 - nm0), f1 = __expf(m1 - nm1);
        float sum0 = 0.f, sum1 = 0.f;
#pragma unroll
        for (int nt = 0; nt < 8; nt++) {
            float p0 = __expf(sacc[nt][0] - nm0);
            float p1 = __expf(sacc[nt][1] - nm0);
            float p2 = __expf(sacc[nt][2] - nm1);
            float p3 = __expf(sacc[nt][3] - nm1);
            sum0 += p0 + p1; sum1 += p2 + p3;
            *(float2*)&Ss[16 * w + gr][nt * 8 + 2 * gc]     = make_float2(p0, p1);
            *(float2*)&Ss[16 * w + gr + 8][nt * 8 + 2 * gc] = make_float2(p2, p3);
        }
        sum0 += __shfl_xor_sync(0xffffffffu, sum0, 1);
        sum0 += __shfl_xor_sync(0xffffffffu, sum0, 2);
        sum1 += __shfl_xor_sync(0xffffffffu, sum1, 1);
        sum1 += __shfl_xor_sync(0xffffffffu, sum1, 2);
        l0 = l0 * f0 + sum0; m0 = nm0;
        l1 = l1 * f1 + sum1; m1 = nm1;
#pragma unroll
        for (int nt = 0; nt < 4; nt++) {
            oa[nt][0] *= f0; oa[nt][1] *= f0;
            oa[nt][2] *= f1; oa[nt][3] *= f1;
        }
        __syncwarp();

        // ---- O += P @ V ----
#pragma unroll
        for (int kk = 0; kk < 8; kk++) {
            uint32_t aF[4];
            aF[0] = __float_as_uint(Ss[16 * w + gr][kk * 8 + gc]);
            aF[1] = __float_as_uint(Ss[16 * w + gr + 8][kk * 8 + gc]);
            aF[2] = __float_as_uint(Ss[16 * w + gr][kk * 8 + gc + 4]);
            aF[3] = __float_as_uint(Ss[16 * w + gr + 8][kk * 8 + gc + 4]);
#pragma unroll
            for (int nt = 0; nt < 4; nt++) {
                uint32_t bF[2];
                bF[0] = __float_as_uint(Vs[buf][kk * 8 + gc][nt * 8 + gr]);
                bF[1] = __float_as_uint(Vs[buf][kk * 8 + gc + 4][nt * 8 + gr]);
                mma_tf32(oa[nt], aF, bF);
            }
        }
        __syncthreads();
        buf ^= 1;
    }

    float inv0 = 1.f / l0, inv1 = 1.f / l1;
    float* obase = O + (((size_t)(s * BB + b)) * NN + qbase) * DIM + h * HD;
#pragma unroll
    for (int nt = 0; nt < 4; nt++) {
        int col = nt * 8 + 2 * gc;
        *(float2*)&obase[(size_t)(16 * w + gr) * DIM + col] =
            make_float2(oa[nt][0] * inv0, oa[nt][1] * inv0);
        *(float2*)&obase[(size_t)(16 * w + gr + 8) * DIM + col] =
            make_float2(oa[nt][2] * inv1, oa[nt][3] * inv1);
    }
}

// ---------------- host orchestration ----------------
static void launch_gemm(int epi, const float* A, const float* W, const float* bias,
                        float* C, int M, int N, int K) {
    dim3 g(N / 128, M / 128);
    if (epi == 0)      gemm_tf32<0><<<g, 256, GEMM_SMEM>>>(A, W, bias, C, M, N, K);
    else if (epi == 1) gemm_tf32<1><<<g, 256, GEMM_SMEM>>>(A, W, bias, C, M, N, K);
    else               gemm_tf32<2><<<g, 256, GEMM_SMEM>>>(A, W, bias, C, M, N, K);
}

extern "C" void kernel_launch(void* const* d_in, const int* in_sizes, int n_in,
                              void* d_out, int out_size) {
    const float* src_feats = (const float*)d_in[0];
    const float* tgt_feats = (const float*)d_in[1];
    const float* src_bias  = (const float*)d_in[2];
    const float* tgt_bias  = (const float*)d_in[3];
    const float* sa_q_w = (const float*)d_in[4];  const float* sa_q_b = (const float*)d_in[5];
    const float* sa_k_w = (const float*)d_in[6];  const float* sa_k_b = (const float*)d_in[7];
    const float* sa_v_w = (const float*)d_in[8];  const float* sa_v_b = (const float*)d_in[9];
    const float* sa_o_w = (const float*)d_in[10]; const float* sa_o_b = (const float*)d_in[11];
    const float* ca_q_w = (const float*)d_in[12]; const float* ca_q_b = (const float*)d_in[13];
    const float* ca_k_w = (const float*)d_in[14]; const float* ca_k_b = (const float*)d_in[15];
    const float* ca_v_w = (const float*)d_in[16]; const float* ca_v_b = (const float*)d_in[17];
    const float* ca_o_w = (const float*)d_in[18]; const float* ca_o_b = (const float*)d_in[19];
    const float* ln_sa_g = (const float*)d_in[20]; const float* ln_sa_b = (const float*)d_in[21];
    const float* ln_ca_g = (const float*)d_in[22]; const float* ln_ca_b = (const float*)d_in[23];
    const float* ln_ff_g = (const float*)d_in[24]; const float* ln_ff_b = (const float*)d_in[25];
    const float* ffn_w1 = (const float*)d_in[26]; const float* ffn_b1 = (const float*)d_in[27];
    const float* ffn_w2 = (const float*)d_in[28]; const float* ffn_b2 = (const float*)d_in[29];

    float* res = (float*)d_out; // [2, B, N, DIM]

    cudaFuncSetAttribute(gemm_tf32<0>, cudaFuncAttributeMaxDynamicSharedMemorySize, GEMM_SMEM);
    cudaFuncSetAttribute(gemm_tf32<1>, cudaFuncAttributeMaxDynamicSharedMemorySize, GEMM_SMEM);
    cudaFuncSetAttribute(gemm_tf32<2>, cudaFuncAttributeMaxDynamicSharedMemorySize, GEMM_SMEM);
    cudaFuncSetAttribute(attn_mma,     cudaFuncAttributeMaxDynamicSharedMemorySize, ATTN_SMEM);

    void *p_xn, *p_q, *p_k, *p_v, *p_ao, *p_h;
    cudaGetSymbolAddress(&p_xn, g_xn);
    cudaGetSymbolAddress(&p_q,  g_q);
    cudaGetSymbolAddress(&p_k,  g_k);
    cudaGetSymbolAddress(&p_v,  g_v);
    cudaGetSymbolAddress(&p_ao, g_ao);
    cudaGetSymbolAddress(&p_h,  g_h);
    float* xn = (float*)p_xn;
    float* qb = (float*)p_q;
    float* kb = (float*)p_k;
    float* vb = (float*)p_v;
    float* ao = (float*)p_ao;
    float* hb = (float*)p_h;

    copy_feats_kernel<<<STREAM_ELEMS / 4 / 256, 256>>>(
        (const float4*)src_feats, (const float4*)tgt_feats, (float4*)res);

    dim3 agrid(NN / 64, HH, 2 * BB);

    // ---- 1. geometric self-attention ----
    ln_kernel<<<MROWS, 256>>>(res, ln_sa_g, ln_sa_b, xn);
    launch_gemm(0, xn, sa_q_w, sa_q_b, qb, MROWS, DIM, DIM);
    launch_gemm(0, xn, sa_k_w, sa_k_b, kb, MROWS, DIM, DIM);
    launch_gemm(0, xn, sa_v_w, sa_v_b, vb, MROWS, DIM, DIM);
    attn_mma<<<agrid, 128, ATTN_SMEM>>>(qb, kb, vb, src_bias, tgt_bias, ao, 0);
    launch_gemm(2, ao, sa_o_w, sa_o_b, res, MROWS, DIM, DIM);

    // ---- 2. cross-attention ----
    ln_kernel<<<MROWS, 256>>>(res, ln_ca_g, ln_ca_b, xn);
    launch_gemm(0, xn, ca_q_w, ca_q_b, qb, MROWS, DIM, DIM);
    launch_gemm(0, xn, ca_k_w, ca_k_b, kb, MROWS, DIM, DIM);
    launch_gemm(0, xn, ca_v_w, ca_v_b, vb, MROWS, DIM, DIM);
    attn_mma<<<agrid, 128, ATTN_SMEM>>>(qb, kb, vb, nullptr, nullptr, ao, 1);
    launch_gemm(2, ao, ca_o_w, ca_o_b, res, MROWS, DIM, DIM);

    // ---- 3. FFN ----
    ln_kernel<<<MROWS, 256>>>(res, ln_ff_g, ln_ff_b, xn);
    launch_gemm(1, xn, ffn_w1, ffn_b1, hb, MROWS, FFN_DIM, DIM);
    launch_gemm(2, hb, ffn_w2, ffn_b2, res, MROWS, DIM, FFN_DIM);
}

// round 6
// speedup vs baseline: 4.0986x; 1.0568x over previous
#include <cuda_runtime.h>
#include <math.h>
#include <stdint.h>

#define BB 4
#define NN 1024
#define DIM 256
#define HH 8
#define HD 32
#define FFN_DIM 1024
#define MROWS (2 * BB * NN)          // 8192 combined rows (src+tgt)
#define STREAM_ELEMS (BB * NN * DIM) // 1048576
#define SCALE 0.17677669529663687f   // 1/sqrt(32)

// ---------------- scratch (static device memory; no allocation) ----------------
__device__ float g_xn[MROWS * DIM];
__device__ float g_q [MROWS * DIM];
__device__ float g_k [MROWS * DIM];
__device__ float g_v [MROWS * DIM];
__device__ float g_ao[MROWS * DIM];
__device__ float g_h [MROWS * FFN_DIM];

// ---------------- residual init: res = feats ----------------
__global__ void copy_feats_kernel(const float4* __restrict__ a,
                                  const float4* __restrict__ b,
                                  float4* __restrict__ out) {
    int i = blockIdx.x * blockDim.x + threadIdx.x;
    out[i] = a[i];
    out[i + STREAM_ELEMS / 4] = b[i];
}

// ---------------- LayerNorm: one block (256 thr) per row ----------------
__global__ __launch_bounds__(256) void ln_kernel(const float* __restrict__ x,
                                                 const float* __restrict__ g,
                                                 const float* __restrict__ bta,
                                                 float* __restrict__ out) {
    int row = blockIdx.x;
    int t = threadIdx.x;
    float v = x[(size_t)row * DIM + t];
    float s = v, s2 = v * v;
#pragma unroll
    for (int o = 16; o; o >>= 1) {
        s  += __shfl_xor_sync(0xffffffffu, s,  o);
        s2 += __shfl_xor_sync(0xffffffffu, s2, o);
    }
    __shared__ float sh[16];
    if ((t & 31) == 0) { sh[t >> 5] = s; sh[8 + (t >> 5)] = s2; }
    __syncthreads();
    float S = 0.f, S2 = 0.f;
#pragma unroll
    for (int w = 0; w < 8; w++) { S += sh[w]; S2 += sh[8 + w]; }
    float mu = S * (1.f / DIM);
    float var = S2 * (1.f / DIM) - mu * mu;
    float r = rsqrtf(var + 1e-5f);
    out[(size_t)row * DIM + t] = (v - mu) * r * g[t] + bta[t];
}

// ---------------- common PTX helpers ----------------
__device__ __forceinline__ float gelu_exact(float x) {
    return 0.5f * x * (1.0f + erff(x * 0.70710678118654752f));
}

__device__ __forceinline__ void cp16(void* dst, const void* src) {
    uint32_t s = (uint32_t)__cvta_generic_to_shared(dst);
    asm volatile("cp.async.cg.shared.global [%0], [%1], 16;" :: "r"(s), "l"(src));
}

__device__ __forceinline__ void mma_tf32(float* d, const uint32_t* a, const uint32_t* b) {
    asm volatile("mma.sync.aligned.m16n8k8.row.col.f32.tf32.tf32.f32 "
        "{%0,%1,%2,%3}, {%4,%5,%6,%7}, {%8,%9}, {%0,%1,%2,%3};"
        : "+f"(d[0]), "+f"(d[1]), "+f"(d[2]), "+f"(d[3])
        : "r"(a[0]), "r"(a[1]), "r"(a[2]), "r"(a[3]), "r"(b[0]), "r"(b[1]));
}

// ---------------- tf32 tensor-core GEMM ----------------
// Block tile 128x64, 8 warps (4 M x 2 N), warp tile 32x32, Kstage 32, double buffer.
// Targets 2 CTAs/SM (regs ~90, smem 54KB).
#define AS_STRIDE 36    // bank = 4m + c : conflict-free frag loads
#define BS_STRIDE 72    // 72 % 32 = 8 : 8k + n covers all banks
#define GEMM_SMEM ((2 * 128 * AS_STRIDE + 2 * 32 * BS_STRIDE) * 4)

template<int EPI>
__global__ __launch_bounds__(256, 2) void gemm_tf32(const float* __restrict__ A,
                                                    const float* __restrict__ W,
                                                    const float* __restrict__ bias,
                                                    float* __restrict__ C,
                                                    int M, int N, int K) {
    extern __shared__ float smem[];
    float (*As)[128][AS_STRIDE] = (float (*)[128][AS_STRIDE])smem;
    float (*Bs)[32][BS_STRIDE]  = (float (*)[32][BS_STRIDE])(smem + 2 * 128 * AS_STRIDE);

    int tid = threadIdx.x;
    int lane = tid & 31, wid = tid >> 5;
    int wm = wid >> 1, wn = wid & 1;       // 4 (M) x 2 (N)
    int gr = lane >> 2, gc = lane & 3;
    int m0 = blockIdx.y * 128, n0 = blockIdx.x * 64;

    int a_r = tid >> 3, a_c = (tid & 7) * 4;   // + i*32 rows (4 cp16)
    int b_r = tid >> 3, b_c = (tid & 7) * 8;   // 2 cp16 per thread

    float acc[2][4][4];
#pragma unroll
    for (int mt = 0; mt < 2; mt++)
#pragma unroll
        for (int nt = 0; nt < 4; nt++)
#pragma unroll
            for (int r = 0; r < 4; r++) acc[mt][nt][r] = 0.f;

    int nstages = K / 32;

#pragma unroll
    for (int i = 0; i < 4; i++)
        cp16(&As[0][a_r + i * 32][a_c], &A[(size_t)(m0 + a_r + i * 32) * K + a_c]);
    cp16(&Bs[0][b_r][b_c],     &W[(size_t)b_r * N + n0 + b_c]);
    cp16(&Bs[0][b_r][b_c + 4], &W[(size_t)b_r * N + n0 + b_c + 4]);
    asm volatile("cp.async.commit_group;");

    int buf = 0;
    for (int s = 0; s < nstages; s++) {
        if (s + 1 < nstages) {
            int k0 = (s + 1) * 32;
#pragma unroll
            for (int i = 0; i < 4; i++)
                cp16(&As[buf ^ 1][a_r + i * 32][a_c],
                     &A[(size_t)(m0 + a_r + i * 32) * K + k0 + a_c]);
            cp16(&Bs[buf ^ 1][b_r][b_c],     &W[(size_t)(k0 + b_r) * N + n0 + b_c]);
            cp16(&Bs[buf ^ 1][b_r][b_c + 4], &W[(size_t)(k0 + b_r) * N + n0 + b_c + 4]);
            asm volatile("cp.async.commit_group;");
            asm volatile("cp.async.wait_group 1;");
        } else {
            asm volatile("cp.async.wait_group 0;");
        }
        __syncthreads();

        int ar0 = wm * 32 + gr;
        int bc0 = wn * 32 + gr;
#pragma unroll
        for (int kk = 0; kk < 4; kk++) {
            int ac = kk * 8 + gc;
            uint32_t aF[2][4], bF[4][2];
#pragma unroll
            for (int mt = 0; mt < 2; mt++) {
                aF[mt][0] = __float_as_uint(As[buf][ar0 + mt * 16][ac]);
                aF[mt][1] = __float_as_uint(As[buf][ar0 + mt * 16 + 8][ac]);
                aF[mt][2] = __float_as_uint(As[buf][ar0 + mt * 16][ac + 4]);
                aF[mt][3] = __float_as_uint(As[buf][ar0 + mt * 16 + 8][ac + 4]);
            }
#pragma unroll
            for (int nt = 0; nt < 4; nt++) {
                bF[nt][0] = __float_as_uint(Bs[buf][ac][bc0 + nt * 8]);
                bF[nt][1] = __float_as_uint(Bs[buf][ac + 4][bc0 + nt * 8]);
            }
#pragma unroll
            for (int mt = 0; mt < 2; mt++)
#pragma unroll
                for (int nt = 0; nt < 4; nt++)
                    mma_tf32(acc[mt][nt], aF[mt], bF[nt]);
        }
        __syncthreads();
        buf ^= 1;
    }

#pragma unroll
    for (int mt = 0; mt < 2; mt++) {
        int mA = m0 + wm * 32 + mt * 16 + gr;
#pragma unroll
        for (int nt = 0; nt < 4; nt++) {
            int n = n0 + wn * 32 + nt * 8 + 2 * gc;
            float bx = bias[n], by = bias[n + 1];
#pragma unroll
            for (int h = 0; h < 2; h++) {
                int m = mA + h * 8;
                float vx = acc[mt][nt][2 * h + 0] + bx;
                float vy = acc[mt][nt][2 * h + 1] + by;
                if (EPI == 1) { vx = gelu_exact(vx); vy = gelu_exact(vy); }
                float2* cp = (float2*)&C[(size_t)m * N + n];
                if (EPI == 2) {
                    float2 old = *cp;
                    vx += old.x; vy += old.y;
                }
                *cp = make_float2(vx, vy);
            }
        }
    }
}

// ---------------- tf32 tensor-core flash attention ----------------
// 128-query tile, 64-key chunks, 8 warps (256 thr). Warp w owns S rows [16w,16w+16).
// smem (floats): Qs[128][36] @0, Ks[2][64][36] @4608, Vs[2][64][40] @9216, Ss[128][68] @14336
#define ATTN_SMEM (23040 * 4)

__global__ __launch_bounds__(256) void attn_mma(const float* __restrict__ Q,
                                                const float* __restrict__ K,
                                                const float* __restrict__ V,
                                                const float* __restrict__ bias0,
                                                const float* __restrict__ bias1,
                                                float* __restrict__ O,
                                                int kvswap) {
    extern __shared__ float sm[];
    float (*Qs)[36]     = (float (*)[36])sm;
    float (*Ks)[64][36] = (float (*)[64][36])(sm + 4608);
    float (*Vs)[64][40] = (float (*)[64][40])(sm + 9216);
    float (*Ss)[68]     = (float (*)[68])(sm + 14336);

    int t = threadIdx.x;
    int lane = t & 31, w = t >> 5;          // 8 warps
    int gr = lane >> 2, gc = lane & 3;
    int qbase = blockIdx.x * 128;
    int h = blockIdx.y;
    int z = blockIdx.z;
    int s = z >> 2, b = z & 3;

    const float* qptr = Q + (((size_t)(s * BB + b)) * NN + qbase) * DIM + h * HD;
    int ks = s ^ kvswap;
    const float* kptr = K + ((size_t)(ks * BB + b)) * NN * DIM + h * HD;
    const float* vptr = V + ((size_t)(ks * BB + b)) * NN * DIM + h * HD;
    const float* bias = kvswap ? nullptr : (s == 0 ? bias0 : bias1);
    const float* bptr = bias ? bias + (((size_t)(b * HH + h)) * NN + qbase) * NN : nullptr;

    // load Q (pre-scaled): 128x32
#pragma unroll
    for (int i = 0; i < 4; i++) {
        int lin = t + i * 256;
        int r = lin >> 3, c = (lin & 7) * 4;
        float4 v4 = *(const float4*)&qptr[(size_t)r * DIM + c];
        Qs[r][c]     = v4.x * SCALE;
        Qs[r][c + 1] = v4.y * SCALE;
        Qs[r][c + 2] = v4.z * SCALE;
        Qs[r][c + 3] = v4.w * SCALE;
    }

    float m0 = -1e30f, m1 = -1e30f, l0 = 0.f, l1 = 0.f;
    float oa[4][4];
#pragma unroll
    for (int nt = 0; nt < 4; nt++)
#pragma unroll
        for (int r = 0; r < 4; r++) oa[nt][r] = 0.f;

    // prologue: chunk 0 -> buf 0 (64x32 each of K,V)
#pragma unroll
    for (int i = 0; i < 2; i++) {
        int lin = t + i * 256;
        int r = lin >> 3, c = (lin & 7) * 4;
        cp16(&Ks[0][r][c], &kptr[(size_t)r * DIM + c]);
        cp16(&Vs[0][r][c], &vptr[(size_t)r * DIM + c]);
    }
    asm volatile("cp.async.commit_group;");

    int buf = 0;
    for (int kc = 0; kc < 16; kc++) {
        int kb = kc * 64;
        if (kc + 1 < 16) {
            int kb2 = (kc + 1) * 64;
#pragma unroll
            for (int i = 0; i < 2; i++) {
                int lin = t + i * 256;
                int r = lin >> 3, c = (lin & 7) * 4;
                cp16(&Ks[buf ^ 1][r][c], &kptr[(size_t)(kb2 + r) * DIM + c]);
                cp16(&Vs[buf ^ 1][r][c], &vptr[(size_t)(kb2 + r) * DIM + c]);
            }
            asm volatile("cp.async.commit_group;");
            asm volatile("cp.async.wait_group 1;");
        } else {
            asm volatile("cp.async.wait_group 0;");
        }
        __syncthreads();

        // ---- S = Q @ K^T (+bias) ----
        float sacc[8][4];
#pragma unroll
        for (int nt = 0; nt < 8; nt++)
#pragma unroll
            for (int r = 0; r < 4; r++) sacc[nt][r] = 0.f;

#pragma unroll
        for (int kk = 0; kk < 4; kk++) {
            uint32_t aF[4];
            aF[0] = __float_as_uint(Qs[16 * w + gr][kk * 8 + gc]);
            aF[1] = __float_as_uint(Qs[16 * w + gr + 8][kk * 8 + gc]);
            aF[2] = __float_as_uint(Qs[16 * w + gr][kk * 8 + gc + 4]);
            aF[3] = __float_as_uint(Qs[16 * w + gr + 8][kk * 8 + gc + 4]);
#pragma unroll
            for (int nt = 0; nt < 8; nt++) {
                uint32_t bF[2];
                bF[0] = __float_as_uint(Ks[buf][nt * 8 + gr][kk * 8 + gc]);
                bF[1] = __float_as_uint(Ks[buf][nt * 8 + gr][kk * 8 + gc + 4]);
                mma_tf32(sacc[nt], aF, bF);
            }
        }
        if (bptr) {
#pragma unroll
            for (int nt = 0; nt < 8; nt++) {
                int col = kb + nt * 8 + 2 * gc;
                float2 u0 = *(const float2*)&bptr[(size_t)(16 * w + gr) * NN + col];
                float2 u1 = *(const float2*)&bptr[(size_t)(16 * w + gr + 8) * NN + col];
                sacc[nt][0] += u0.x; sacc[nt][1] += u0.y;
                sacc[nt][2] += u1.x; sacc[nt][3] += u1.y;
            }
        }

        // ---- online softmax (rows 16w+gr, 16w+gr+8; quad-local) ----
        float cm0 = -1e30f, cm1 = -1e30f;
#pragma unroll
        for (int nt = 0; nt < 8; nt++) {
            cm0 = fmaxf(cm0, fmaxf(sacc[nt][0], sacc[nt][1]));
            cm1 = fmaxf(cm1, fmaxf(sacc[nt][2], sacc[nt][3]));
        }
        cm0 = fmaxf(cm0, __shfl_xor_sync(0xffffffffu, cm0, 1));
        cm0 = fmaxf(cm0, __shfl_xor_sync(0xffffffffu, cm0, 2));
        cm1 = fmaxf(cm1, __shfl_xor_sync(0xffffffffu, cm1, 1));
        cm1 = fmaxf(cm1, __shfl_xor_sync(0xffffffffu, cm1, 2));
        float nm0 = fmaxf(m0, cm0), nm1 = fmaxf(m1, cm1);
        float f0 = __expf(m0 - nm0), f1 = __expf(m1 - nm1);
        float sum0 = 0.f, sum1 = 0.f;
#pragma unroll
        for (int nt = 0; nt < 8; nt++) {
            float p0 = __expf(sacc[nt][0] - nm0);
            float p1 = __expf(sacc[nt][1] - nm0);
            float p2 = __expf(sacc[nt][2] - nm1);
            float p3 = __expf(sacc[nt][3] - nm1);
            sum0 += p0 + p1; sum1 += p2 + p3;
            *(float2*)&Ss[16 * w + gr][nt * 8 + 2 * gc]     = make_float2(p0, p1);
            *(float2*)&Ss[16 * w + gr + 8][nt * 8 + 2 * gc] = make_float2(p2, p3);
        }
        sum0 += __shfl_xor_sync(0xffffffffu, sum0, 1);
        sum0 += __shfl_xor_sync(0xffffffffu, sum0, 2);
        sum1 += __shfl_xor_sync(0xffffffffu, sum1, 1);
        sum1 += __shfl_xor_sync(0xffffffffu, sum1, 2);
        l0 = l0 * f0 + sum0; m0 = nm0;
        l1 = l1 * f1 + sum1; m1 = nm1;
#pragma unroll
        for (int nt = 0; nt < 4; nt++) {
            oa[nt][0] *= f0; oa[nt][1] *= f0;
            oa[nt][2] *= f1; oa[nt][3] *= f1;
        }
        __syncwarp();

        // ---- O += P @ V ----
#pragma unroll
        for (int kk = 0; kk < 8; kk++) {
            uint32_t aF[4];
            aF[0] = __float_as_uint(Ss[16 * w + gr][kk * 8 + gc]);
            aF[1] = __float_as_uint(Ss[16 * w + gr + 8][kk * 8 + gc]);
            aF[2] = __float_as_uint(Ss[16 * w + gr][kk * 8 + gc + 4]);
            aF[3] = __float_as_uint(Ss[16 * w + gr + 8][kk * 8 + gc + 4]);
#pragma unroll
            for (int nt = 0; nt < 4; nt++) {
                uint32_t bF[2];
                bF[0] = __float_as_uint(Vs[buf][kk * 8 + gc][nt * 8 + gr]);
                bF[1] = __float_as_uint(Vs[buf][kk * 8 + gc + 4][nt * 8 + gr]);
                mma_tf32(oa[nt], aF, bF);
            }
        }
        __syncthreads();
        buf ^= 1;
    }

    float inv0 = 1.f / l0, inv1 = 1.f / l1;
    float* obase = O + (((size_t)(s * BB + b)) * NN + qbase) * DIM + h * HD;
#pragma unroll
    for (int nt = 0; nt < 4; nt++) {
        int col = nt * 8 + 2 * gc;
        *(float2*)&obase[(size_t)(16 * w + gr) * DIM + col] =
            make_float2(oa[nt][0] * inv0, oa[nt][1] * inv0);
        *(float2*)&obase[(size_t)(16 * w + gr + 8) * DIM + col] =
            make_float2(oa[nt][2] * inv1, oa[nt][3] * inv1);
    }
}

// ---------------- host orchestration ----------------
static void launch_gemm(int epi, const float* A, const float* W, const float* bias,
                        float* C, int M, int N, int K) {
    dim3 g(N / 64, M / 128);
    if (epi == 0)      gemm_tf32<0><<<g, 256, GEMM_SMEM>>>(A, W, bias, C, M, N, K);
    else if (epi == 1) gemm_tf32<1><<<g, 256, GEMM_SMEM>>>(A, W, bias, C, M, N, K);
    else               gemm_tf32<2><<<g, 256, GEMM_SMEM>>>(A, W, bias, C, M, N, K);
}

extern "C" void kernel_launch(void* const* d_in, const int* in_sizes, int n_in,
                              void* d_out, int out_size) {
    const float* src_feats = (const float*)d_in[0];
    const float* tgt_feats = (const float*)d_in[1];
    const float* src_bias  = (const float*)d_in[2];
    const float* tgt_bias  = (const float*)d_in[3];
    const float* sa_q_w = (const float*)d_in[4];  const float* sa_q_b = (const float*)d_in[5];
    const float* sa_k_w = (const float*)d_in[6];  const float* sa_k_b = (const float*)d_in[7];
    const float* sa_v_w = (const float*)d_in[8];  const float* sa_v_b = (const float*)d_in[9];
    const float* sa_o_w = (const float*)d_in[10]; const float* sa_o_b = (const float*)d_in[11];
    const float* ca_q_w = (const float*)d_in[12]; const float* ca_q_b = (const float*)d_in[13];
    const float* ca_k_w = (const float*)d_in[14]; const float* ca_k_b = (const float*)d_in[15];
    const float* ca_v_w = (const float*)d_in[16]; const float* ca_v_b = (const float*)d_in[17];
    const float* ca_o_w = (const float*)d_in[18]; const float* ca_o_b = (const float*)d_in[19];
    const float* ln_sa_g = (const float*)d_in[20]; const float* ln_sa_b = (const float*)d_in[21];
    const float* ln_ca_g = (const float*)d_in[22]; const float* ln_ca_b = (const float*)d_in[23];
    const float* ln_ff_g = (const float*)d_in[24]; const float* ln_ff_b = (const float*)d_in[25];
    const float* ffn_w1 = (const float*)d_in[26]; const float* ffn_b1 = (const float*)d_in[27];
    const float* ffn_w2 = (const float*)d_in[28]; const float* ffn_b2 = (const float*)d_in[29];

    float* res = (float*)d_out; // [2, B, N, DIM]

    cudaFuncSetAttribute(gemm_tf32<0>, cudaFuncAttributeMaxDynamicSharedMemorySize, GEMM_SMEM);
    cudaFuncSetAttribute(gemm_tf32<1>, cudaFuncAttributeMaxDynamicSharedMemorySize, GEMM_SMEM);
    cudaFuncSetAttribute(gemm_tf32<2>, cudaFuncAttributeMaxDynamicSharedMemorySize, GEMM_SMEM);
    cudaFuncSetAttribute(attn_mma,     cudaFuncAttributeMaxDynamicSharedMemorySize, ATTN_SMEM);

    void *p_xn, *p_q, *p_k, *p_v, *p_ao, *p_h;
    cudaGetSymbolAddress(&p_xn, g_xn);
    cudaGetSymbolAddress(&p_q,  g_q);
    cudaGetSymbolAddress(&p_k,  g_k);
    cudaGetSymbolAddress(&p_v,  g_v);
    cudaGetSymbolAddress(&p_ao, g_ao);
    cudaGetSymbolAddress(&p_h,  g_h);
    float* xn = (float*)p_xn;
    float* qb = (float*)p_q;
    float* kb = (float*)p_k;
    float* vb = (float*)p_v;
    float* ao = (float*)p_ao;
    float* hb = (float*)p_h;

    copy_feats_kernel<<<STREAM_ELEMS / 4 / 256, 256>>>(
        (const float4*)src_feats, (const float4*)tgt_feats, (float4*)res);

    dim3 agrid(NN / 128, HH, 2 * BB);

    // ---- 1. geometric self-attention ----
    ln_kernel<<<MROWS, 256>>>(res, ln_sa_g, ln_sa_b, xn);
    launch_gemm(0, xn, sa_q_w, sa_q_b, qb, MROWS, DIM, DIM);
    launch_gemm(0, xn, sa_k_w, sa_k_b, kb, MROWS, DIM, DIM);
    launch_gemm(0, xn, sa_v_w, sa_v_b, vb, MROWS, DIM, DIM);
    attn_mma<<<agrid, 256, ATTN_SMEM>>>(qb, kb, vb, src_bias, tgt_bias, ao, 0);
    launch_gemm(2, ao, sa_o_w, sa_o_b, res, MROWS, DIM, DIM);

    // ---- 2. cross-attention ----
    ln_kernel<<<MROWS, 256>>>(res, ln_ca_g, ln_ca_b, xn);
    launch_gemm(0, xn, ca_q_w, ca_q_b, qb, MROWS, DIM, DIM);
    launch_gemm(0, xn, ca_k_w, ca_k_b, kb, MROWS, DIM, DIM);
    launch_gemm(0, xn, ca_v_w, ca_v_b, vb, MROWS, DIM, DIM);
    attn_mma<<<agrid, 256, ATTN_SMEM>>>(qb, kb, vb, nullptr, nullptr, ao, 1);
    launch_gemm(2, ao, ca_o_w, ca_o_b, res, MROWS, DIM, DIM);

    // ---- 3. FFN ----
    ln_kernel<<<MROWS, 256>>>(res, ln_ff_g, ln_ff_b, xn);
    launch_gemm(1, xn, ffn_w1, ffn_b1, hb, MROWS, FFN_DIM, DIM);
    launch_gemm(2, hb, ffn_w2, ffn_b2, res, MROWS, DIM, FFN_DIM);
}

// round 7
// speedup vs baseline: 5.5204x; 1.3469x over previous
#include <cuda_runtime.h>
#include <cuda_fp16.h>
#include <math.h>
#include <stdint.h>

#define BB 4
#define NN 1024
#define DIM 256
#define HH 8
#define HD 32
#define FFN_DIM 1024
#define MROWS (2 * BB * NN)          // 8192 combined rows (src+tgt)
#define STREAM_ELEMS (BB * NN * DIM) // 1048576
#define SCALE 0.17677669529663687f   // 1/sqrt(32)

// ---------------- scratch (static device memory; no allocation) ----------------
__device__ __half g_xn[MROWS * DIM];
__device__ __half g_qh[MROWS * DIM];
__device__ __half g_kh[MROWS * DIM];
__device__ __half g_vh[MROWS * DIM];
__device__ __half g_ao[MROWS * DIM];
__device__ __half g_hh[MROWS * FFN_DIM];
__device__ __half g_wt[8 * 65536 + 2 * 262144]; // transposed fp16 weights [N][K]

// ---------------- residual init: res = feats ----------------
__global__ void copy_feats_kernel(const float4* __restrict__ a,
                                  const float4* __restrict__ b,
                                  float4* __restrict__ out) {
    int i = blockIdx.x * blockDim.x + threadIdx.x;
    out[i] = a[i];
    out[i + STREAM_ELEMS / 4] = b[i];
}

// ---------------- weight transpose + fp16 convert: W[K,N] -> Wt[N,K] ----------------
struct WList {
    const float* src[10];
    __half* dst[10];
    int K[10];
    int N[10];
};

__global__ __launch_bounds__(256) void wcvt_kernel(WList wl) {
    int wi = blockIdx.z;
    const float* W = wl.src[wi];
    __half* Wt = wl.dst[wi];
    int K = wl.K[wi], N = wl.N[wi];
    int n0 = blockIdx.x * 32, k0 = blockIdx.y * 32;
    if (n0 >= N || k0 >= K) return;
    __shared__ float tile[32][33];
    int tx = threadIdx.x & 31, ty = threadIdx.x >> 5; // 32 x 8
#pragma unroll
    for (int i = 0; i < 32; i += 8)
        tile[ty + i][tx] = W[(size_t)(k0 + ty + i) * N + n0 + tx];
    __syncthreads();
#pragma unroll
    for (int i = 0; i < 32; i += 8)
        Wt[(size_t)(n0 + ty + i) * K + k0 + tx] = __float2half(tile[tx][ty + i]);
}

// ---------------- LayerNorm: one block (256 thr) per row, fp16 out ----------------
__global__ __launch_bounds__(256) void ln_kernel(const float* __restrict__ x,
                                                 const float* __restrict__ g,
                                                 const float* __restrict__ bta,
                                                 __half* __restrict__ out) {
    int row = blockIdx.x;
    int t = threadIdx.x;
    float v = x[(size_t)row * DIM + t];
    float s = v, s2 = v * v;
#pragma unroll
    for (int o = 16; o; o >>= 1) {
        s  += __shfl_xor_sync(0xffffffffu, s,  o);
        s2 += __shfl_xor_sync(0xffffffffu, s2, o);
    }
    __shared__ float sh[16];
    if ((t & 31) == 0) { sh[t >> 5] = s; sh[8 + (t >> 5)] = s2; }
    __syncthreads();
    float S = 0.f, S2 = 0.f;
#pragma unroll
    for (int w = 0; w < 8; w++) { S += sh[w]; S2 += sh[8 + w]; }
    float mu = S * (1.f / DIM);
    float var = S2 * (1.f / DIM) - mu * mu;
    float r = rsqrtf(var + 1e-5f);
    out[(size_t)row * DIM + t] = __float2half((v - mu) * r * g[t] + bta[t]);
}

// ---------------- common PTX helpers ----------------
__device__ __forceinline__ float gelu_exact(float x) {
    return 0.5f * x * (1.0f + erff(x * 0.70710678118654752f));
}

__device__ __forceinline__ void cp16(void* dst, const void* src) {
    uint32_t s = (uint32_t)__cvta_generic_to_shared(dst);
    asm volatile("cp.async.cg.shared.global [%0], [%1], 16;" :: "r"(s), "l"(src));
}

__device__ __forceinline__ void mma_f16(float* d, const uint32_t* a, const uint32_t* b) {
    asm volatile("mma.sync.aligned.m16n8k16.row.col.f32.f16.f16.f32 "
        "{%0,%1,%2,%3}, {%4,%5,%6,%7}, {%8,%9}, {%0,%1,%2,%3};"
        : "+f"(d[0]), "+f"(d[1]), "+f"(d[2]), "+f"(d[3])
        : "r"(a[0]), "r"(a[1]), "r"(a[2]), "r"(a[3]), "r"(b[0]), "r"(b[1]));
}

// ---------------- fp16 tensor-core GEMM ----------------
// C[M,N] = A[M,K](fp16) @ Wt[N,K](fp16)^T + bias
// EPI: 0 = bias->fp16 out, 1 = bias+gelu->fp16 out, 2 = bias+residual->fp32 out,
//      3 = (bias)*SCALE->fp16 out (q projection)
// Block 128x64, 8 warps (4M x 2N), warp 32x32, K-stage 32 (2 x k16), double buffer.
#define ASTR 40   // half stride (80B): conflict-free
#define GEMM_SMEM ((2 * 128 * ASTR + 2 * 64 * ASTR) * 2)

template<int EPI>
__global__ __launch_bounds__(256, 2) void gemm_f16(const __half* __restrict__ A,
                                                   const __half* __restrict__ Wt,
                                                   const float* __restrict__ bias,
                                                   void* __restrict__ Cv,
                                                   int M, int N, int K) {
    extern __shared__ __half smh[];
    __half (*As)[128][ASTR] = (__half (*)[128][ASTR])smh;
    __half (*Bs)[64][ASTR]  = (__half (*)[64][ASTR])(smh + 2 * 128 * ASTR);

    int tid = threadIdx.x;
    int lane = tid & 31, wid = tid >> 5;
    int wm = wid >> 1, wn = wid & 1;       // 4 (M) x 2 (N)
    int gr = lane >> 2, gc = lane & 3;
    int m0 = blockIdx.y * 128, n0 = blockIdx.x * 64;

    int a_r = tid >> 1, a_c = (tid & 1) * 16;   // 2 cp16 (at +0, +8)
    int b_r = tid >> 2, b_c = (tid & 3) * 8;    // 1 cp16

    float acc[2][4][4];
#pragma unroll
    for (int mt = 0; mt < 2; mt++)
#pragma unroll
        for (int nt = 0; nt < 4; nt++)
#pragma unroll
            for (int r = 0; r < 4; r++) acc[mt][nt][r] = 0.f;

    int nstages = K / 32;

    cp16(&As[0][a_r][a_c],     &A[(size_t)(m0 + a_r) * K + a_c]);
    cp16(&As[0][a_r][a_c + 8], &A[(size_t)(m0 + a_r) * K + a_c + 8]);
    cp16(&Bs[0][b_r][b_c],     &Wt[(size_t)(n0 + b_r) * K + b_c]);
    asm volatile("cp.async.commit_group;");

    int buf = 0;
    for (int s = 0; s < nstages; s++) {
        if (s + 1 < nstages) {
            int k0 = (s + 1) * 32;
            cp16(&As[buf ^ 1][a_r][a_c],     &A[(size_t)(m0 + a_r) * K + k0 + a_c]);
            cp16(&As[buf ^ 1][a_r][a_c + 8], &A[(size_t)(m0 + a_r) * K + k0 + a_c + 8]);
            cp16(&Bs[buf ^ 1][b_r][b_c],     &Wt[(size_t)(n0 + b_r) * K + k0 + b_c]);
            asm volatile("cp.async.commit_group;");
            asm volatile("cp.async.wait_group 1;");
        } else {
            asm volatile("cp.async.wait_group 0;");
        }
        __syncthreads();

        int ar0 = wm * 32 + gr;
        int bn0 = wn * 32 + gr;
#pragma unroll
        for (int kk = 0; kk < 2; kk++) {
            int kc = kk * 16 + 2 * gc;
            uint32_t aF[2][4], bF[4][2];
#pragma unroll
            for (int mt = 0; mt < 2; mt++) {
                aF[mt][0] = *(const uint32_t*)&As[buf][ar0 + mt * 16][kc];
                aF[mt][1] = *(const uint32_t*)&As[buf][ar0 + mt * 16 + 8][kc];
                aF[mt][2] = *(const uint32_t*)&As[buf][ar0 + mt * 16][kc + 8];
                aF[mt][3] = *(const uint32_t*)&As[buf][ar0 + mt * 16 + 8][kc + 8];
            }
#pragma unroll
            for (int nt = 0; nt < 4; nt++) {
                bF[nt][0] = *(const uint32_t*)&Bs[buf][bn0 + nt * 8][kc];
                bF[nt][1] = *(const uint32_t*)&Bs[buf][bn0 + nt * 8][kc + 8];
            }
#pragma unroll
            for (int mt = 0; mt < 2; mt++)
#pragma unroll
                for (int nt = 0; nt < 4; nt++)
                    mma_f16(acc[mt][nt], aF[mt], bF[nt]);
        }
        __syncthreads();
        buf ^= 1;
    }

    // epilogue: C layout c0=(gr,2gc) c1=(gr,2gc+1) c2=(gr+8,2gc) c3=(gr+8,2gc+1)
#pragma unroll
    for (int mt = 0; mt < 2; mt++) {
        int mA = m0 + wm * 32 + mt * 16 + gr;
#pragma unroll
        for (int nt = 0; nt < 4; nt++) {
            int n = n0 + wn * 32 + nt * 8 + 2 * gc;
            float bx = bias[n], by = bias[n + 1];
#pragma unroll
            for (int h = 0; h < 2; h++) {
                int m = mA + h * 8;
                float vx = acc[mt][nt][2 * h + 0] + bx;
                float vy = acc[mt][nt][2 * h + 1] + by;
                if (EPI == 1) { vx = gelu_exact(vx); vy = gelu_exact(vy); }
                if (EPI == 3) { vx *= SCALE; vy *= SCALE; }
                if (EPI == 2) {
                    float2* cp = (float2*)&((float*)Cv)[(size_t)m * N + n];
                    float2 old = *cp;
                    *cp = make_float2(vx + old.x, vy + old.y);
                } else {
                    *(__half2*)&((__half*)Cv)[(size_t)m * N + n] = __floats2half2_rn(vx, vy);
                }
            }
        }
    }
}

// ---------------- fp16 tensor-core flash attention ----------------
// 128-query tile, 64-key chunks, 8 warps. Warp w owns S rows [16w,16w+16).
// smem halves: Qs[128][40], Ks[2][64][40], Vs[2][64][40], Ss[128][72]
#define ATTN_SMEM ((128 * 40 + 2 * 64 * 40 + 2 * 64 * 40 + 128 * 72) * 2)

__global__ __launch_bounds__(256) void attn_mma(const __half* __restrict__ Q,
                                                const __half* __restrict__ K,
                                                const __half* __restrict__ V,
                                                const float* __restrict__ bias0,
                                                const float* __restrict__ bias1,
                                                __half* __restrict__ O,
                                                int kvswap) {
    extern __shared__ __half smh[];
    __half (*Qs)[40]     = (__half (*)[40])smh;
    __half (*Ks)[64][40] = (__half (*)[64][40])(smh + 128 * 40);
    __half (*Vs)[64][40] = (__half (*)[64][40])(smh + 128 * 40 + 2 * 64 * 40);
    __half (*Ss)[72]     = (__half (*)[72])(smh + 128 * 40 + 4 * 64 * 40);

    int t = threadIdx.x;
    int lane = t & 31, w = t >> 5;
    int gr = lane >> 2, gc = lane & 3;
    int qbase = blockIdx.x * 128;
    int h = blockIdx.y;
    int z = blockIdx.z;
    int s = z >> 2, b = z & 3;

    const __half* qptr = Q + (((size_t)(s * BB + b)) * NN + qbase) * DIM + h * HD;
    int ks = s ^ kvswap;
    const __half* kptr = K + ((size_t)(ks * BB + b)) * NN * DIM + h * HD;
    const __half* vptr = V + ((size_t)(ks * BB + b)) * NN * DIM + h * HD;
    const float* bias = kvswap ? nullptr : (s == 0 ? bias0 : bias1);
    const float* bptr = bias ? bias + (((size_t)(b * HH + h)) * NN + qbase) * NN : nullptr;

    // Q: 128x32 halves (already scaled by q-proj epilogue)
    {
        int r = t >> 1, c = (t & 1) * 16;
        cp16(&Qs[r][c],     &qptr[(size_t)r * DIM + c]);
        cp16(&Qs[r][c + 8], &qptr[(size_t)r * DIM + c + 8]);
    }
    // K/V chunk 0
    {
        int r = t >> 2, c = (t & 3) * 8;
        cp16(&Ks[0][r][c], &kptr[(size_t)r * DIM + c]);
        cp16(&Vs[0][r][c], &vptr[(size_t)r * DIM + c]);
    }
    asm volatile("cp.async.commit_group;");

    float m0 = -1e30f, m1 = -1e30f, l0 = 0.f, l1 = 0.f;
    float oa[4][4];
#pragma unroll
    for (int nt = 0; nt < 4; nt++)
#pragma unroll
        for (int r = 0; r < 4; r++) oa[nt][r] = 0.f;

    int r0 = 16 * w + gr, r1 = 16 * w + gr + 8;

    int buf = 0;
    for (int kc = 0; kc < 16; kc++) {
        int kb = kc * 64;
        if (kc + 1 < 16) {
            int kb2 = (kc + 1) * 64;
            int r = t >> 2, c = (t & 3) * 8;
            cp16(&Ks[buf ^ 1][r][c], &kptr[(size_t)(kb2 + r) * DIM + c]);
            cp16(&Vs[buf ^ 1][r][c], &vptr[(size_t)(kb2 + r) * DIM + c]);
            asm volatile("cp.async.commit_group;");
            asm volatile("cp.async.wait_group 1;");
        } else {
            asm volatile("cp.async.wait_group 0;");
        }
        __syncthreads();

        // ---- S = Q @ K^T (+bias) : m16 x n64, k=32 ----
        float sacc[8][4];
#pragma unroll
        for (int nt = 0; nt < 8; nt++)
#pragma unroll
            for (int r = 0; r < 4; r++) sacc[nt][r] = 0.f;

#pragma unroll
        for (int kk = 0; kk < 2; kk++) {
            int kcd = kk * 16 + 2 * gc;
            uint32_t aF[4];
            aF[0] = *(const uint32_t*)&Qs[r0][kcd];
            aF[1] = *(const uint32_t*)&Qs[r1][kcd];
            aF[2] = *(const uint32_t*)&Qs[r0][kcd + 8];
            aF[3] = *(const uint32_t*)&Qs[r1][kcd + 8];
#pragma unroll
            for (int nt = 0; nt < 8; nt++) {
                uint32_t bF[2];
                bF[0] = *(const uint32_t*)&Ks[buf][nt * 8 + gr][kcd];
                bF[1] = *(const uint32_t*)&Ks[buf][nt * 8 + gr][kcd + 8];
                mma_f16(sacc[nt], aF, bF);
            }
        }
        if (bptr) {
#pragma unroll
            for (int nt = 0; nt < 8; nt++) {
                int col = kb + nt * 8 + 2 * gc;
                float2 u0 = *(const float2*)&bptr[(size_t)r0 * NN + col];
                float2 u1 = *(const float2*)&bptr[(size_t)r1 * NN + col];
                sacc[nt][0] += u0.x; sacc[nt][1] += u0.y;
                sacc[nt][2] += u1.x; sacc[nt][3] += u1.y;
            }
        }

        // ---- online softmax (rows r0, r1; quad-local) ----
        float cm0 = -1e30f, cm1 = -1e30f;
#pragma unroll
        for (int nt = 0; nt < 8; nt++) {
            cm0 = fmaxf(cm0, fmaxf(sacc[nt][0], sacc[nt][1]));
            cm1 = fmaxf(cm1, fmaxf(sacc[nt][2], sacc[nt][3]));
        }
        cm0 = fmaxf(cm0, __shfl_xor_sync(0xffffffffu, cm0, 1));
        cm0 = fmaxf(cm0, __shfl_xor_sync(0xffffffffu, cm0, 2));
        cm1 = fmaxf(cm1, __shfl_xor_sync(0xffffffffu, cm1, 1));
        cm1 = fmaxf(cm1, __shfl_xor_sync(0xffffffffu, cm1, 2));
        float nm0 = fmaxf(m0, cm0), nm1 = fmaxf(m1, cm1);
        float f0 = __expf(m0 - nm0), f1 = __expf(m1 - nm1);
        float sum0 = 0.f, sum1 = 0.f;
#pragma unroll
        for (int nt = 0; nt < 8; nt++) {
            float p0 = __expf(sacc[nt][0] - nm0);
            float p1 = __expf(sacc[nt][1] - nm0);
            float p2 = __expf(sacc[nt][2] - nm1);
            float p3 = __expf(sacc[nt][3] - nm1);
            sum0 += p0 + p1; sum1 += p2 + p3;
            *(__half2*)&Ss[r0][nt * 8 + 2 * gc] = __floats2half2_rn(p0, p1);
            *(__half2*)&Ss[r1][nt * 8 + 2 * gc] = __floats2half2_rn(p2, p3);
        }
        sum0 += __shfl_xor_sync(0xffffffffu, sum0, 1);
        sum0 += __shfl_xor_sync(0xffffffffu, sum0, 2);
        sum1 += __shfl_xor_sync(0xffffffffu, sum1, 1);
        sum1 += __shfl_xor_sync(0xffffffffu, sum1, 2);
        l0 = l0 * f0 + sum0; m0 = nm0;
        l1 = l1 * f1 + sum1; m1 = nm1;
#pragma unroll
        for (int nt = 0; nt < 4; nt++) {
            oa[nt][0] *= f0; oa[nt][1] *= f0;
            oa[nt][2] *= f1; oa[nt][3] *= f1;
        }
        __syncwarp();

        // ---- O += P @ V : m16 x n32, k=64 ----
#pragma unroll
        for (int kk = 0; kk < 4; kk++) {
            int kcd = kk * 16 + 2 * gc;
            uint32_t aF[4];
            aF[0] = *(const uint32_t*)&Ss[r0][kcd];
            aF[1] = *(const uint32_t*)&Ss[r1][kcd];
            aF[2] = *(const uint32_t*)&Ss[r0][kcd + 8];
            aF[3] = *(const uint32_t*)&Ss[r1][kcd + 8];
            // per-lane ldmatrix row for V (x2.trans): rows k = kk*16 + (lane&15)
            uint32_t vrow_addr = (uint32_t)__cvta_generic_to_shared(
                &Vs[buf][kk * 16 + (lane & 15)][0]);
#pragma unroll
            for (int nt = 0; nt < 4; nt++) {
                uint32_t bF[2];
                asm volatile("ldmatrix.sync.aligned.m8n8.x2.trans.shared.b16 {%0,%1}, [%2];"
                             : "=r"(bF[0]), "=r"(bF[1])
                             : "r"(vrow_addr + nt * 16));
                mma_f16(oa[nt], aF, bF);
            }
        }
        __syncthreads();
        buf ^= 1;
    }

    float inv0 = 1.f / l0, inv1 = 1.f / l1;
    __half* obase = O + (((size_t)(s * BB + b)) * NN + qbase) * DIM + h * HD;
#pragma unroll
    for (int nt = 0; nt < 4; nt++) {
        int col = nt * 8 + 2 * gc;
        *(__half2*)&obase[(size_t)r0 * DIM + col] =
            __floats2half2_rn(oa[nt][0] * inv0, oa[nt][1] * inv0);
        *(__half2*)&obase[(size_t)r1 * DIM + col] =
            __floats2half2_rn(oa[nt][2] * inv1, oa[nt][3] * inv1);
    }
}

// ---------------- host orchestration ----------------
static void launch_gemm(int epi, const __half* A, const __half* Wt, const float* bias,
                        void* C, int M, int N, int K) {
    dim3 g(N / 64, M / 128);
    if (epi == 0)      gemm_f16<0><<<g, 256, GEMM_SMEM>>>(A, Wt, bias, C, M, N, K);
    else if (epi == 1) gemm_f16<1><<<g, 256, GEMM_SMEM>>>(A, Wt, bias, C, M, N, K);
    else if (epi == 2) gemm_f16<2><<<g, 256, GEMM_SMEM>>>(A, Wt, bias, C, M, N, K);
    else               gemm_f16<3><<<g, 256, GEMM_SMEM>>>(A, Wt, bias, C, M, N, K);
}

extern "C" void kernel_launch(void* const* d_in, const int* in_sizes, int n_in,
                              void* d_out, int out_size) {
    const float* src_feats = (const float*)d_in[0];
    const float* tgt_feats = (const float*)d_in[1];
    const float* src_bias  = (const float*)d_in[2];
    const float* tgt_bias  = (const float*)d_in[3];
    const float* sa_q_w = (const float*)d_in[4];  const float* sa_q_b = (const float*)d_in[5];
    const float* sa_k_w = (const float*)d_in[6];  const float* sa_k_b = (const float*)d_in[7];
    const float* sa_v_w = (const float*)d_in[8];  const float* sa_v_b = (const float*)d_in[9];
    const float* sa_o_w = (const float*)d_in[10]; const float* sa_o_b = (const float*)d_in[11];
    const float* ca_q_w = (const float*)d_in[12]; const float* ca_q_b = (const float*)d_in[13];
    const float* ca_k_w = (const float*)d_in[14]; const float* ca_k_b = (const float*)d_in[15];
    const float* ca_v_w = (const float*)d_in[16]; const float* ca_v_b = (const float*)d_in[17];
    const float* ca_o_w = (const float*)d_in[18]; const float* ca_o_b = (const float*)d_in[19];
    const float* ln_sa_g = (const float*)d_in[20]; const float* ln_sa_b = (const float*)d_in[21];
    const float* ln_ca_g = (const float*)d_in[22]; const float* ln_ca_b = (const float*)d_in[23];
    const float* ln_ff_g = (const float*)d_in[24]; const float* ln_ff_b = (const float*)d_in[25];
    const float* ffn_w1 = (const float*)d_in[26]; const float* ffn_b1 = (const float*)d_in[27];
    const float* ffn_w2 = (const float*)d_in[28]; const float* ffn_b2 = (const float*)d_in[29];

    float* res = (float*)d_out; // [2, B, N, DIM]

    cudaFuncSetAttribute(gemm_f16<0>, cudaFuncAttributeMaxDynamicSharedMemorySize, GEMM_SMEM);
    cudaFuncSetAttribute(gemm_f16<1>, cudaFuncAttributeMaxDynamicSharedMemorySize, GEMM_SMEM);
    cudaFuncSetAttribute(gemm_f16<2>, cudaFuncAttributeMaxDynamicSharedMemorySize, GEMM_SMEM);
    cudaFuncSetAttribute(gemm_f16<3>, cudaFuncAttributeMaxDynamicSharedMemorySize, GEMM_SMEM);
    cudaFuncSetAttribute(attn_mma,    cudaFuncAttributeMaxDynamicSharedMemorySize, ATTN_SMEM);

    void *p_xn, *p_q, *p_k, *p_v, *p_ao, *p_h, *p_wt;
    cudaGetSymbolAddress(&p_xn, g_xn);
    cudaGetSymbolAddress(&p_q,  g_qh);
    cudaGetSymbolAddress(&p_k,  g_kh);
    cudaGetSymbolAddress(&p_v,  g_vh);
    cudaGetSymbolAddress(&p_ao, g_ao);
    cudaGetSymbolAddress(&p_h,  g_hh);
    cudaGetSymbolAddress(&p_wt, g_wt);
    __half* xn = (__half*)p_xn;
    __half* qb = (__half*)p_q;
    __half* kb = (__half*)p_k;
    __half* vb = (__half*)p_v;
    __half* ao = (__half*)p_ao;
    __half* hb = (__half*)p_h;
    __half* wt = (__half*)p_wt;

    // transposed fp16 weight table
    __half* wt_saq = wt;
    __half* wt_sak = wt + 1 * 65536;
    __half* wt_sav = wt + 2 * 65536;
    __half* wt_sao = wt + 3 * 65536;
    __half* wt_caq = wt + 4 * 65536;
    __half* wt_cak = wt + 5 * 65536;
    __half* wt_cav = wt + 6 * 65536;
    __half* wt_cao = wt + 7 * 65536;
    __half* wt_w1  = wt + 8 * 65536;            // [1024][256]
    __half* wt_w2  = wt + 8 * 65536 + 262144;   // [256][1024]

    WList wl;
    const float* srcs[10] = {sa_q_w, sa_k_w, sa_v_w, sa_o_w, ca_q_w, ca_k_w, ca_v_w, ca_o_w,
                             ffn_w1, ffn_w2};
    __half* dsts[10] = {wt_saq, wt_sak, wt_sav, wt_sao, wt_caq, wt_cak, wt_cav, wt_cao,
                        wt_w1, wt_w2};
    int Ks[10] = {256, 256, 256, 256, 256, 256, 256, 256, 256, 1024};
    int Ns[10] = {256, 256, 256, 256, 256, 256, 256, 256, 1024, 256};
    for (int i = 0; i < 10; i++) { wl.src[i] = srcs[i]; wl.dst[i] = dsts[i]; wl.K[i] = Ks[i]; wl.N[i] = Ns[i]; }
    wcvt_kernel<<<dim3(32, 32, 10), 256>>>(wl);

    copy_feats_kernel<<<STREAM_ELEMS / 4 / 256, 256>>>(
        (const float4*)src_feats, (const float4*)tgt_feats, (float4*)res);

    dim3 agrid(NN / 128, HH, 2 * BB);

    // ---- 1. geometric self-attention ----
    ln_kernel<<<MROWS, 256>>>(res, ln_sa_g, ln_sa_b, xn);
    launch_gemm(3, xn, wt_saq, sa_q_b, qb, MROWS, DIM, DIM);   // q, pre-scaled
    launch_gemm(0, xn, wt_sak, sa_k_b, kb, MROWS, DIM, DIM);
    launch_gemm(0, xn, wt_sav, sa_v_b, vb, MROWS, DIM, DIM);
    attn_mma<<<agrid, 256, ATTN_SMEM>>>(qb, kb, vb, src_bias, tgt_bias, ao, 0);
    launch_gemm(2, ao, wt_sao, sa_o_b, res, MROWS, DIM, DIM);

    // ---- 2. cross-attention ----
    ln_kernel<<<MROWS, 256>>>(res, ln_ca_g, ln_ca_b, xn);
    launch_gemm(3, xn, wt_caq, ca_q_b, qb, MROWS, DIM, DIM);
    launch_gemm(0, xn, wt_cak, ca_k_b, kb, MROWS, DIM, DIM);
    launch_gemm(0, xn, wt_cav, ca_v_b, vb, MROWS, DIM, DIM);
    attn_mma<<<agrid, 256, ATTN_SMEM>>>(qb, kb, vb, nullptr, nullptr, ao, 1);
    launch_gemm(2, ao, wt_cao, ca_o_b, res, MROWS, DIM, DIM);

    // ---- 3. FFN ----
    ln_kernel<<<MROWS, 256>>>(res, ln_ff_g, ln_ff_b, xn);
    launch_gemm(1, xn, wt_w1, ffn_b1, hb, MROWS, FFN_DIM, DIM);
    launch_gemm(2, hb, wt_w2, ffn_b2, res, MROWS, DIM, FFN_DIM);
}

// round 8
// speedup vs baseline: 5.6791x; 1.0288x over previous
#include <cuda_runtime.h>
#include <cuda_fp16.h>
#include <math.h>
#include <stdint.h>

#define BB 4
#define NN 1024
#define DIM 256
#define HH 8
#define HD 32
#define FFN_DIM 1024
#define MROWS (2 * BB * NN)          // 8192 combined rows (src+tgt)
#define STREAM_ELEMS (BB * NN * DIM) // 1048576
#define SCALE 0.17677669529663687f   // 1/sqrt(32)
#define QKV 768

// ---------------- scratch (static device memory; no allocation) ----------------
__device__ __half g_xn [MROWS * DIM];
__device__ __half g_qkv[MROWS * QKV];     // packed q|k|v rows
__device__ __half g_ao [MROWS * DIM];
__device__ __half g_hh [MROWS * FFN_DIM];
__device__ __half g_wt [1048576];         // fp16 weights, transposed [N][K]
__device__ float  g_bqkv[2 * QKV];        // fused qkv bias (sa, ca)

// ---------------- residual init: res = feats ----------------
__global__ void copy_feats_kernel(const float4* __restrict__ a,
                                  const float4* __restrict__ b,
                                  float4* __restrict__ out) {
    int i = blockIdx.x * blockDim.x + threadIdx.x;
    out[i] = a[i];
    out[i + STREAM_ELEMS / 4] = b[i];
}

// ---------------- weight transpose + fp16 convert: W[K,N] -> Wt[N,K] ----------------
struct WList {
    const float* src[10];
    __half* dst[10];
    int K[10];
    int N[10];
};

__global__ __launch_bounds__(256) void wcvt_kernel(WList wl) {
    int wi = blockIdx.z;
    const float* W = wl.src[wi];
    __half* Wt = wl.dst[wi];
    int K = wl.K[wi], N = wl.N[wi];
    int n0 = blockIdx.x * 32, k0 = blockIdx.y * 32;
    if (n0 >= N || k0 >= K) return;
    __shared__ float tile[32][33];
    int tx = threadIdx.x & 31, ty = threadIdx.x >> 5; // 32 x 8
#pragma unroll
    for (int i = 0; i < 32; i += 8)
        tile[ty + i][tx] = W[(size_t)(k0 + ty + i) * N + n0 + tx];
    __syncthreads();
#pragma unroll
    for (int i = 0; i < 32; i += 8)
        Wt[(size_t)(n0 + ty + i) * K + k0 + tx] = __float2half(tile[tx][ty + i]);
}

// ---------------- fused qkv bias ----------------
__global__ void bias_fuse_kernel(const float* qb, const float* kb, const float* vb,
                                 const float* qb2, const float* kb2, const float* vb2,
                                 float* dst) {
    int i = threadIdx.x;                 // 0..767
    const float* s[6] = {qb, kb, vb, qb2, kb2, vb2};
    dst[blockIdx.x * QKV + i] = s[blockIdx.x * 3 + i / 256][i & 255];
}

// ---------------- LayerNorm: one block (256 thr) per row, fp16 out ----------------
__global__ __launch_bounds__(256) void ln_kernel(const float* __restrict__ x,
                                                 const float* __restrict__ g,
                                                 const float* __restrict__ bta,
                                                 __half* __restrict__ out) {
    int row = blockIdx.x;
    int t = threadIdx.x;
    float v = x[(size_t)row * DIM + t];
    float s = v, s2 = v * v;
#pragma unroll
    for (int o = 16; o; o >>= 1) {
        s  += __shfl_xor_sync(0xffffffffu, s,  o);
        s2 += __shfl_xor_sync(0xffffffffu, s2, o);
    }
    __shared__ float sh[16];
    if ((t & 31) == 0) { sh[t >> 5] = s; sh[8 + (t >> 5)] = s2; }
    __syncthreads();
    float S = 0.f, S2 = 0.f;
#pragma unroll
    for (int w = 0; w < 8; w++) { S += sh[w]; S2 += sh[8 + w]; }
    float mu = S * (1.f / DIM);
    float var = S2 * (1.f / DIM) - mu * mu;
    float r = rsqrtf(var + 1e-5f);
    out[(size_t)row * DIM + t] = __float2half((v - mu) * r * g[t] + bta[t]);
}

// ---------------- common PTX helpers ----------------
__device__ __forceinline__ float gelu_exact(float x) {
    return 0.5f * x * (1.0f + erff(x * 0.70710678118654752f));
}

__device__ __forceinline__ void cp16(void* dst, const void* src) {
    uint32_t s = (uint32_t)__cvta_generic_to_shared(dst);
    asm volatile("cp.async.cg.shared.global [%0], [%1], 16;" :: "r"(s), "l"(src));
}

__device__ __forceinline__ void mma_f16(float* d, const uint32_t* a, const uint32_t* b) {
    asm volatile("mma.sync.aligned.m16n8k16.row.col.f32.f16.f16.f32 "
        "{%0,%1,%2,%3}, {%4,%5,%6,%7}, {%8,%9}, {%0,%1,%2,%3};"
        : "+f"(d[0]), "+f"(d[1]), "+f"(d[2]), "+f"(d[3])
        : "r"(a[0]), "r"(a[1]), "r"(a[2]), "r"(a[3]), "r"(b[0]), "r"(b[1]));
}

__device__ __forceinline__ void ldm4(uint32_t* r, const __half* p) {
    uint32_t a = (uint32_t)__cvta_generic_to_shared(p);
    asm volatile("ldmatrix.sync.aligned.m8n8.x4.shared.b16 {%0,%1,%2,%3}, [%4];"
        : "=r"(r[0]), "=r"(r[1]), "=r"(r[2]), "=r"(r[3]) : "r"(a));
}

// ---------------- fp16 tensor-core GEMM (ldmatrix mainloop) ----------------
// C[M,N] = A[M,K](fp16) @ Wt[N,K](fp16)^T + bias
// EPI: 0 = bias->fp16, 1 = bias+gelu->fp16, 2 = bias+residual->fp32,
//      3 = qkv-fused: fp16 out, (acc+bias)*SCALE for n<256
// Block 128x64, 8 warps (4M x 2N), warp 32x32, K-stage 64, double buffer.
#define ASTR 72   // halves (144 B): ldmatrix 8-row access conflict-free
#define GEMM_SMEM ((2 * 128 * ASTR + 2 * 64 * ASTR) * 2)

template<int EPI>
__global__ __launch_bounds__(256, 2) void gemm_f16(const __half* __restrict__ A,
                                                   const __half* __restrict__ Wt,
                                                   const float* __restrict__ bias,
                                                   void* __restrict__ Cv,
                                                   int M, int N, int K) {
    extern __shared__ __half smh[];
    __half (*As)[128][ASTR] = (__half (*)[128][ASTR])smh;
    __half (*Bs)[64][ASTR]  = (__half (*)[64][ASTR])(smh + 2 * 128 * ASTR);

    int tid = threadIdx.x;
    int lane = tid & 31, wid = tid >> 5;
    int wm = wid >> 1, wn = wid & 1;       // 4 (M) x 2 (N)
    int gr = lane >> 2, gc = lane & 3;
    int m0 = blockIdx.y * 128, n0 = blockIdx.x * 64;

    // gmem->smem: A 4 cp16/thread, B 2 cp16/thread (64 k-halves per stage)
    int a_r = tid >> 1, a_c = (tid & 1) * 32;
    int b_r = tid >> 2, b_c = (tid & 3) * 16;

    // ldmatrix lane addressing
    int lar = wm * 32 + (lane & 15);           // A row (+ mt*16)
    int lak = (lane >> 4) * 8;                 // A k-offset (+ kk*16)
    int lbr = wn * 32 + (lane >> 4) * 8 + (lane & 7);  // B row (+ ntp*16)
    int lbk = ((lane >> 3) & 1) * 8;           // B k-offset (+ kk*16)

    float acc[2][4][4];
#pragma unroll
    for (int mt = 0; mt < 2; mt++)
#pragma unroll
        for (int nt = 0; nt < 4; nt++)
#pragma unroll
            for (int r = 0; r < 4; r++) acc[mt][nt][r] = 0.f;

    int nstages = K / 64;

#pragma unroll
    for (int j = 0; j < 4; j++)
        cp16(&As[0][a_r][a_c + j * 8], &A[(size_t)(m0 + a_r) * K + a_c + j * 8]);
#pragma unroll
    for (int j = 0; j < 2; j++)
        cp16(&Bs[0][b_r][b_c + j * 8], &Wt[(size_t)(n0 + b_r) * K + b_c + j * 8]);
    asm volatile("cp.async.commit_group;");

    int buf = 0;
    for (int s = 0; s < nstages; s++) {
        if (s + 1 < nstages) {
            int k0 = (s + 1) * 64;
#pragma unroll
            for (int j = 0; j < 4; j++)
                cp16(&As[buf ^ 1][a_r][a_c + j * 8],
                     &A[(size_t)(m0 + a_r) * K + k0 + a_c + j * 8]);
#pragma unroll
            for (int j = 0; j < 2; j++)
                cp16(&Bs[buf ^ 1][b_r][b_c + j * 8],
                     &Wt[(size_t)(n0 + b_r) * K + k0 + b_c + j * 8]);
            asm volatile("cp.async.commit_group;");
            asm volatile("cp.async.wait_group 1;");
        } else {
            asm volatile("cp.async.wait_group 0;");
        }
        __syncthreads();

#pragma unroll
        for (int kk = 0; kk < 4; kk++) {
            uint32_t aF[2][4], b01[4], b23[4];
            ldm4(aF[0], &As[buf][lar][kk * 16 + lak]);
            ldm4(aF[1], &As[buf][lar + 16][kk * 16 + lak]);
            ldm4(b01, &Bs[buf][lbr][kk * 16 + lbk]);
            ldm4(b23, &Bs[buf][lbr + 16][kk * 16 + lbk]);
#pragma unroll
            for (int mt = 0; mt < 2; mt++) {
                mma_f16(acc[mt][0], aF[mt], &b01[0]);
                mma_f16(acc[mt][1], aF[mt], &b01[2]);
                mma_f16(acc[mt][2], aF[mt], &b23[0]);
                mma_f16(acc[mt][3], aF[mt], &b23[2]);
            }
        }
        __syncthreads();
        buf ^= 1;
    }

    // epilogue: acc layout c0=(gr,2gc) c1=(gr,2gc+1) c2=(gr+8,2gc) c3=(gr+8,2gc+1)
#pragma unroll
    for (int mt = 0; mt < 2; mt++) {
        int mA = m0 + wm * 32 + mt * 16 + gr;
#pragma unroll
        for (int nt = 0; nt < 4; nt++) {
            int n = n0 + wn * 32 + nt * 8 + 2 * gc;
            float bx = bias[n], by = bias[n + 1];
            float sc = (EPI == 3 && n < 256) ? SCALE : 1.0f;
#pragma unroll
            for (int h = 0; h < 2; h++) {
                int m = mA + h * 8;
                float vx = acc[mt][nt][2 * h + 0] + bx;
                float vy = acc[mt][nt][2 * h + 1] + by;
                if (EPI == 1) { vx = gelu_exact(vx); vy = gelu_exact(vy); }
                if (EPI == 3) { vx *= sc; vy *= sc; }
                if (EPI == 2) {
                    float2* cp = (float2*)&((float*)Cv)[(size_t)m * N + n];
                    float2 old = *cp;
                    *cp = make_float2(vx + old.x, vy + old.y);
                } else {
                    *(__half2*)&((__half*)Cv)[(size_t)m * N + n] = __floats2half2_rn(vx, vy);
                }
            }
        }
    }
}

// ---------------- fp16 flash attention (ldmatrix fragments) ----------------
// 128-query tile, 64-key chunks, 8 warps. Warp w owns S rows [16w,16w+16).
// Reads packed qkv[M][768]: q at +0 (pre-scaled), k at +256, v at +512.
#define SSTR 72
#define ATTN_SMEM ((128 * 40 + 2 * 64 * 40 + 2 * 64 * 40 + 128 * SSTR) * 2)

__global__ __launch_bounds__(256) void attn_mma(const __half* __restrict__ QKVp,
                                                const float* __restrict__ bias0,
                                                const float* __restrict__ bias1,
                                                __half* __restrict__ O,
                                                int kvswap) {
    extern __shared__ __half smh[];
    __half (*Qs)[40]      = (__half (*)[40])smh;
    __half (*Ks)[64][40]  = (__half (*)[64][40])(smh + 128 * 40);
    __half (*Vs)[64][40]  = (__half (*)[64][40])(smh + 128 * 40 + 2 * 64 * 40);
    __half (*Ss)[SSTR]    = (__half (*)[SSTR])(smh + 128 * 40 + 4 * 64 * 40);

    int t = threadIdx.x;
    int lane = t & 31, w = t >> 5;
    int gr = lane >> 2, gc = lane & 3;
    int qbase = blockIdx.x * 128;
    int h = blockIdx.y;
    int z = blockIdx.z;
    int s = z >> 2, b = z & 3;

    const __half* qptr = QKVp + (((size_t)(s * BB + b)) * NN + qbase) * QKV + h * HD;
    int ks = s ^ kvswap;
    const __half* kptr = QKVp + ((size_t)(ks * BB + b)) * NN * QKV + 256 + h * HD;
    const __half* vptr = QKVp + ((size_t)(ks * BB + b)) * NN * QKV + 512 + h * HD;
    const float* bias = kvswap ? nullptr : (s == 0 ? bias0 : bias1);
    const float* bptr = bias ? bias + (((size_t)(b * HH + h)) * NN + qbase) * NN : nullptr;

    // Q: 128x32 halves (already scaled)
    {
        int r = t >> 1, c = (t & 1) * 16;
        cp16(&Qs[r][c],     &qptr[(size_t)r * QKV + c]);
        cp16(&Qs[r][c + 8], &qptr[(size_t)r * QKV + c + 8]);
    }
    // K/V chunk 0
    {
        int r = t >> 2, c = (t & 3) * 8;
        cp16(&Ks[0][r][c], &kptr[(size_t)r * QKV + c]);
        cp16(&Vs[0][r][c], &vptr[(size_t)r * QKV + c]);
    }
    asm volatile("cp.async.commit_group;");

    float m0 = -1e30f, m1 = -1e30f, l0 = 0.f, l1 = 0.f;
    float oa[4][4];
#pragma unroll
    for (int nt = 0; nt < 4; nt++)
#pragma unroll
        for (int r = 0; r < 4; r++) oa[nt][r] = 0.f;

    int r0 = 16 * w + gr, r1 = 16 * w + gr + 8;
    int lqr = 16 * w + (lane & 15);        // ldmatrix rows for Q/S frags
    int lqk = (lane >> 4) * 8;
    int lkr = (lane >> 4) * 8 + (lane & 7); // K frag rows (+ ntp*16)
    int lkk = ((lane >> 3) & 1) * 8;

    int buf = 0;
    for (int kc = 0; kc < 16; kc++) {
        int kb = kc * 64;
        if (kc + 1 < 16) {
            int kb2 = (kc + 1) * 64;
            int r = t >> 2, c = (t & 3) * 8;
            cp16(&Ks[buf ^ 1][r][c], &kptr[(size_t)(kb2 + r) * QKV + c]);
            cp16(&Vs[buf ^ 1][r][c], &vptr[(size_t)(kb2 + r) * QKV + c]);
            asm volatile("cp.async.commit_group;");
            asm volatile("cp.async.wait_group 1;");
        } else {
            asm volatile("cp.async.wait_group 0;");
        }
        __syncthreads();

        // ---- S = Q @ K^T (+bias) : m16 x n64, k=32 ----
        float sacc[8][4];
#pragma unroll
        for (int nt = 0; nt < 8; nt++)
#pragma unroll
            for (int r = 0; r < 4; r++) sacc[nt][r] = 0.f;

#pragma unroll
        for (int kk = 0; kk < 2; kk++) {
            uint32_t aF[4];
            ldm4(aF, &Qs[lqr][kk * 16 + lqk]);
#pragma unroll
            for (int ntp = 0; ntp < 4; ntp++) {
                uint32_t bP[4];
                ldm4(bP, &Ks[buf][ntp * 16 + lkr][kk * 16 + lkk]);
                mma_f16(sacc[ntp * 2 + 0], aF, &bP[0]);
                mma_f16(sacc[ntp * 2 + 1], aF, &bP[2]);
            }
        }
        if (bptr) {
#pragma unroll
            for (int nt = 0; nt < 8; nt++) {
                int col = kb + nt * 8 + 2 * gc;
                float2 u0 = *(const float2*)&bptr[(size_t)r0 * NN + col];
                float2 u1 = *(const float2*)&bptr[(size_t)r1 * NN + col];
                sacc[nt][0] += u0.x; sacc[nt][1] += u0.y;
                sacc[nt][2] += u1.x; sacc[nt][3] += u1.y;
            }
        }

        // ---- online softmax (rows r0, r1; quad-local) ----
        float cm0 = -1e30f, cm1 = -1e30f;
#pragma unroll
        for (int nt = 0; nt < 8; nt++) {
            cm0 = fmaxf(cm0, fmaxf(sacc[nt][0], sacc[nt][1]));
            cm1 = fmaxf(cm1, fmaxf(sacc[nt][2], sacc[nt][3]));
        }
        cm0 = fmaxf(cm0, __shfl_xor_sync(0xffffffffu, cm0, 1));
        cm0 = fmaxf(cm0, __shfl_xor_sync(0xffffffffu, cm0, 2));
        cm1 = fmaxf(cm1, __shfl_xor_sync(0xffffffffu, cm1, 1));
        cm1 = fmaxf(cm1, __shfl_xor_sync(0xffffffffu, cm1, 2));
        float nm0 = fmaxf(m0, cm0), nm1 = fmaxf(m1, cm1);
        float f0 = __expf(m0 - nm0), f1 = __expf(m1 - nm1);
        float sum0 = 0.f, sum1 = 0.f;
#pragma unroll
        for (int nt = 0; nt < 8; nt++) {
            float p0 = __expf(sacc[nt][0] - nm0);
            float p1 = __expf(sacc[nt][1] - nm0);
            float p2 = __expf(sacc[nt][2] - nm1);
            float p3 = __expf(sacc[nt][3] - nm1);
            sum0 += p0 + p1; sum1 += p2 + p3;
            *(__half2*)&Ss[r0][nt * 8 + 2 * gc] = __floats2half2_rn(p0, p1);
            *(__half2*)&Ss[r1][nt * 8 + 2 * gc] = __floats2half2_rn(p2, p3);
        }
        sum0 += __shfl_xor_sync(0xffffffffu, sum0, 1);
        sum0 += __shfl_xor_sync(0xffffffffu, sum0, 2);
        sum1 += __shfl_xor_sync(0xffffffffu, sum1, 1);
        sum1 += __shfl_xor_sync(0xffffffffu, sum1, 2);
        l0 = l0 * f0 + sum0; m0 = nm0;
        l1 = l1 * f1 + sum1; m1 = nm1;
#pragma unroll
        for (int nt = 0; nt < 4; nt++) {
            oa[nt][0] *= f0; oa[nt][1] *= f0;
            oa[nt][2] *= f1; oa[nt][3] *= f1;
        }
        __syncwarp();

        // ---- O += P @ V : m16 x n32, k=64 ----
#pragma unroll
        for (int kk = 0; kk < 4; kk++) {
            uint32_t aF[4];
            ldm4(aF, &Ss[lqr][kk * 16 + lqk]);
            uint32_t vrow_addr = (uint32_t)__cvta_generic_to_shared(
                &Vs[buf][kk * 16 + (lane & 15)][0]);
#pragma unroll
            for (int nt = 0; nt < 4; nt++) {
                uint32_t bF[2];
                asm volatile("ldmatrix.sync.aligned.m8n8.x2.trans.shared.b16 {%0,%1}, [%2];"
                             : "=r"(bF[0]), "=r"(bF[1])
                             : "r"(vrow_addr + nt * 16));
                mma_f16(oa[nt], aF, bF);
            }
        }
        __syncthreads();
        buf ^= 1;
    }

    float inv0 = 1.f / l0, inv1 = 1.f / l1;
    __half* obase = O + (((size_t)(s * BB + b)) * NN + qbase) * DIM + h * HD;
#pragma unroll
    for (int nt = 0; nt < 4; nt++) {
        int col = nt * 8 + 2 * gc;
        *(__half2*)&obase[(size_t)r0 * DIM + col] =
            __floats2half2_rn(oa[nt][0] * inv0, oa[nt][1] * inv0);
        *(__half2*)&obase[(size_t)r1 * DIM + col] =
            __floats2half2_rn(oa[nt][2] * inv1, oa[nt][3] * inv1);
    }
}

// ---------------- host orchestration ----------------
static void launch_gemm(int epi, const __half* A, const __half* Wt, const float* bias,
                        void* C, int M, int N, int K) {
    dim3 g(N / 64, M / 128);
    if (epi == 0)      gemm_f16<0><<<g, 256, GEMM_SMEM>>>(A, Wt, bias, C, M, N, K);
    else if (epi == 1) gemm_f16<1><<<g, 256, GEMM_SMEM>>>(A, Wt, bias, C, M, N, K);
    else if (epi == 2) gemm_f16<2><<<g, 256, GEMM_SMEM>>>(A, Wt, bias, C, M, N, K);
    else               gemm_f16<3><<<g, 256, GEMM_SMEM>>>(A, Wt, bias, C, M, N, K);
}

extern "C" void kernel_launch(void* const* d_in, const int* in_sizes, int n_in,
                              void* d_out, int out_size) {
    const float* src_feats = (const float*)d_in[0];
    const float* tgt_feats = (const float*)d_in[1];
    const float* src_bias  = (const float*)d_in[2];
    const float* tgt_bias  = (const float*)d_in[3];
    const float* sa_q_w = (const float*)d_in[4];  const float* sa_q_b = (const float*)d_in[5];
    const float* sa_k_w = (const float*)d_in[6];  const float* sa_k_b = (const float*)d_in[7];
    const float* sa_v_w = (const float*)d_in[8];  const float* sa_v_b = (const float*)d_in[9];
    const float* sa_o_w = (const float*)d_in[10]; const float* sa_o_b = (const float*)d_in[11];
    const float* ca_q_w = (const float*)d_in[12]; const float* ca_q_b = (const float*)d_in[13];
    const float* ca_k_w = (const float*)d_in[14]; const float* ca_k_b = (const float*)d_in[15];
    const float* ca_v_w = (const float*)d_in[16]; const float* ca_v_b = (const float*)d_in[17];
    const float* ca_o_w = (const float*)d_in[18]; const float* ca_o_b = (const float*)d_in[19];
    const float* ln_sa_g = (const float*)d_in[20]; const float* ln_sa_b = (const float*)d_in[21];
    const float* ln_ca_g = (const float*)d_in[22]; const float* ln_ca_b = (const float*)d_in[23];
    const float* ln_ff_g = (const float*)d_in[24]; const float* ln_ff_b = (const float*)d_in[25];
    const float* ffn_w1 = (const float*)d_in[26]; const float* ffn_b1 = (const float*)d_in[27];
    const float* ffn_w2 = (const float*)d_in[28]; const float* ffn_b2 = (const float*)d_in[29];

    float* res = (float*)d_out; // [2, B, N, DIM]

    cudaFuncSetAttribute(gemm_f16<0>, cudaFuncAttributeMaxDynamicSharedMemorySize, GEMM_SMEM);
    cudaFuncSetAttribute(gemm_f16<1>, cudaFuncAttributeMaxDynamicSharedMemorySize, GEMM_SMEM);
    cudaFuncSetAttribute(gemm_f16<2>, cudaFuncAttributeMaxDynamicSharedMemorySize, GEMM_SMEM);
    cudaFuncSetAttribute(gemm_f16<3>, cudaFuncAttributeMaxDynamicSharedMemorySize, GEMM_SMEM);
    cudaFuncSetAttribute(attn_mma,    cudaFuncAttributeMaxDynamicSharedMemorySize, ATTN_SMEM);

    void *p_xn, *p_qkv, *p_ao, *p_h, *p_wt, *p_bq;
    cudaGetSymbolAddress(&p_xn,  g_xn);
    cudaGetSymbolAddress(&p_qkv, g_qkv);
    cudaGetSymbolAddress(&p_ao,  g_ao);
    cudaGetSymbolAddress(&p_h,   g_hh);
    cudaGetSymbolAddress(&p_wt,  g_wt);
    cudaGetSymbolAddress(&p_bq,  g_bqkv);
    __half* xn  = (__half*)p_xn;
    __half* qkv = (__half*)p_qkv;
    __half* ao  = (__half*)p_ao;
    __half* hb  = (__half*)p_h;
    __half* wt  = (__half*)p_wt;
    float*  bq  = (float*)p_bq;

    // weight table: sa qkv fused [768][256], ca qkv fused [768][256], o x2, w1, w2
    __half* wt_saqkv = wt;                        // 196608
    __half* wt_caqkv = wt + 196608;               // 196608
    __half* wt_sao   = wt + 393216;               // 65536
    __half* wt_cao   = wt + 458752;               // 65536
    __half* wt_w1    = wt + 524288;               // 262144 [1024][256]
    __half* wt_w2    = wt + 786432;               // 262144 [256][1024]

    WList wl;
    const float* srcs[10] = {sa_q_w, sa_k_w, sa_v_w, ca_q_w, ca_k_w, ca_v_w,
                             sa_o_w, ca_o_w, ffn_w1, ffn_w2};
    __half* dsts[10] = {wt_saqkv, wt_saqkv + 256 * 256, wt_saqkv + 512 * 256,
                        wt_caqkv, wt_caqkv + 256 * 256, wt_caqkv + 512 * 256,
                        wt_sao, wt_cao, wt_w1, wt_w2};
    int Ksz[10] = {256, 256, 256, 256, 256, 256, 256, 256, 256, 1024};
    int Nsz[10] = {256, 256, 256, 256, 256, 256, 256, 256, 1024, 256};
    for (int i = 0; i < 10; i++) { wl.src[i] = srcs[i]; wl.dst[i] = dsts[i]; wl.K[i] = Ksz[i]; wl.N[i] = Nsz[i]; }
    wcvt_kernel<<<dim3(32, 32, 10), 256>>>(wl);
    bias_fuse_kernel<<<2, QKV>>>(sa_q_b, sa_k_b, sa_v_b, ca_q_b, ca_k_b, ca_v_b, bq);

    copy_feats_kernel<<<STREAM_ELEMS / 4 / 256, 256>>>(
        (const float4*)src_feats, (const float4*)tgt_feats, (float4*)res);

    dim3 agrid(NN / 128, HH, 2 * BB);

    // ---- 1. geometric self-attention ----
    ln_kernel<<<MROWS, 256>>>(res, ln_sa_g, ln_sa_b, xn);
    launch_gemm(3, xn, wt_saqkv, bq, qkv, MROWS, QKV, DIM);
    attn_mma<<<agrid, 256, ATTN_SMEM>>>(qkv, src_bias, tgt_bias, ao, 0);
    launch_gemm(2, ao, wt_sao, sa_o_b, res, MROWS, DIM, DIM);

    // ---- 2. cross-attention ----
    ln_kernel<<<MROWS, 256>>>(res, ln_ca_g, ln_ca_b, xn);
    launch_gemm(3, xn, wt_caqkv, bq + QKV, qkv, MROWS, QKV, DIM);
    attn_mma<<<agrid, 256, ATTN_SMEM>>>(qkv, nullptr, nullptr, ao, 1);
    launch_gemm(2, ao, wt_cao, ca_o_b, res, MROWS, DIM, DIM);

    // ---- 3. FFN ----
    ln_kernel<<<MROWS, 256>>>(res, ln_ff_g, ln_ff_b, xn);
    launch_gemm(1, xn, wt_w1, ffn_b1, hb, MROWS, FFN_DIM, DIM);
    launch_gemm(2, hb, wt_w2, ffn_b2, res, MROWS, DIM, FFN_DIM);
}

// round 13
// speedup vs baseline: 6.2424x; 1.0992x over previous
#include <cuda_runtime.h>
#include <cuda_fp16.h>
#include <math.h>
#include <stdint.h>

#define BB 4
#define NN 1024
#define DIM 256
#define HH 8
#define HD 32
#define FFN_DIM 1024
#define MROWS (2 * BB * NN)          // 8192 combined rows (src+tgt)
#define STREAM_ELEMS (BB * NN * DIM) // 1048576
#define SCALE 0.17677669529663687f   // 1/sqrt(32)
#define QKV 768

// ---------------- scratch (static device memory; no allocation) ----------------
__device__ __half g_xn [MROWS * DIM];
__device__ __half g_qkv[MROWS * QKV];     // packed q|k|v rows
__device__ __half g_ao [MROWS * DIM];
__device__ __half g_hh [MROWS * FFN_DIM];
__device__ __half g_wt [1048576];         // fp16 weights, transposed [N][K]
__device__ float  g_bqkv[2 * QKV];        // fused qkv bias (sa, ca)

// ---------------- residual init: res = feats ----------------
__global__ void copy_feats_kernel(const float4* __restrict__ a,
                                  const float4* __restrict__ b,
                                  float4* __restrict__ out) {
    int i = blockIdx.x * blockDim.x + threadIdx.x;
    out[i] = a[i];
    out[i + STREAM_ELEMS / 4] = b[i];
}

// ---------------- weight transpose + fp16 convert: W[K,N] -> Wt[N,K] ----------------
struct WList {
    const float* src[10];
    __half* dst[10];
    int K[10];
    int N[10];
};

__global__ __launch_bounds__(256) void wcvt_kernel(WList wl) {
    int wi = blockIdx.z;
    const float* W = wl.src[wi];
    __half* Wt = wl.dst[wi];
    int K = wl.K[wi], N = wl.N[wi];
    int n0 = blockIdx.x * 32, k0 = blockIdx.y * 32;
    if (n0 >= N || k0 >= K) return;
    __shared__ float tile[32][33];
    int tx = threadIdx.x & 31, ty = threadIdx.x >> 5; // 32 x 8
#pragma unroll
    for (int i = 0; i < 32; i += 8)
        tile[ty + i][tx] = W[(size_t)(k0 + ty + i) * N + n0 + tx];
    __syncthreads();
#pragma unroll
    for (int i = 0; i < 32; i += 8)
        Wt[(size_t)(n0 + ty + i) * K + k0 + tx] = __float2half(tile[tx][ty + i]);
}

// ---------------- fused qkv bias ----------------
__global__ void bias_fuse_kernel(const float* qb, const float* kb, const float* vb,
                                 const float* qb2, const float* kb2, const float* vb2,
                                 float* dst) {
    int i = threadIdx.x;                 // 0..767
    const float* s[6] = {qb, kb, vb, qb2, kb2, vb2};
    dst[blockIdx.x * QKV + i] = s[blockIdx.x * 3 + i / 256][i & 255];
}

// ---------------- LayerNorm: one block (256 thr) per row, fp16 out ----------------
__global__ __launch_bounds__(256) void ln_kernel(const float* __restrict__ x,
                                                 const float* __restrict__ g,
                                                 const float* __restrict__ bta,
                                                 __half* __restrict__ out) {
    int row = blockIdx.x;
    int t = threadIdx.x;
    float v = x[(size_t)row * DIM + t];
    float s = v, s2 = v * v;
#pragma unroll
    for (int o = 16; o; o >>= 1) {
        s  += __shfl_xor_sync(0xffffffffu, s,  o);
        s2 += __shfl_xor_sync(0xffffffffu, s2, o);
    }
    __shared__ float sh[16];
    if ((t & 31) == 0) { sh[t >> 5] = s; sh[8 + (t >> 5)] = s2; }
    __syncthreads();
    float S = 0.f, S2 = 0.f;
#pragma unroll
    for (int w = 0; w < 8; w++) { S += sh[w]; S2 += sh[8 + w]; }
    float mu = S * (1.f / DIM);
    float var = S2 * (1.f / DIM) - mu * mu;
    float r = rsqrtf(var + 1e-5f);
    out[(size_t)row * DIM + t] = __float2half((v - mu) * r * g[t] + bta[t]);
}

// ---------------- common PTX helpers ----------------
__device__ __forceinline__ float gelu_exact(float x) {
    return 0.5f * x * (1.0f + erff(x * 0.70710678118654752f));
}

__device__ __forceinline__ uint32_t half2_bits(__half2 h) {
    return *(uint32_t*)&h;
}

__device__ __forceinline__ void cp16(void* dst, const void* src) {
    uint32_t s = (uint32_t)__cvta_generic_to_shared(dst);
    asm volatile("cp.async.cg.shared.global [%0], [%1], 16;" :: "r"(s), "l"(src));
}

__device__ __forceinline__ void mma_f16(float* d, const uint32_t* a, const uint32_t* b) {
    asm volatile("mma.sync.aligned.m16n8k16.row.col.f32.f16.f16.f32 "
        "{%0,%1,%2,%3}, {%4,%5,%6,%7}, {%8,%9}, {%0,%1,%2,%3};"
        : "+f"(d[0]), "+f"(d[1]), "+f"(d[2]), "+f"(d[3])
        : "r"(a[0]), "r"(a[1]), "r"(a[2]), "r"(a[3]), "r"(b[0]), "r"(b[1]));
}

__device__ __forceinline__ void ldm4(uint32_t* r, const __half* p) {
    uint32_t a = (uint32_t)__cvta_generic_to_shared(p);
    asm volatile("ldmatrix.sync.aligned.m8n8.x4.shared.b16 {%0,%1,%2,%3}, [%4];"
        : "=r"(r[0]), "=r"(r[1]), "=r"(r[2]), "=r"(r[3]) : "r"(a));
}

__device__ __forceinline__ void ldm4t(uint32_t* r, const __half* p) {
    uint32_t a = (uint32_t)__cvta_generic_to_shared(p);
    asm volatile("ldmatrix.sync.aligned.m8n8.x4.trans.shared.b16 {%0,%1,%2,%3}, [%4];"
        : "=r"(r[0]), "=r"(r[1]), "=r"(r[2]), "=r"(r[3]) : "r"(a));
}

// ---------------- fp16 tensor-core GEMM (ldmatrix mainloop, 3-stage cp.async) ----------------
// C[M,N] = A[M,K](fp16) @ Wt[N,K](fp16)^T + bias
// EPI: 0 = bias->fp16, 1 = bias+gelu->fp16, 2 = bias+residual->fp32,
//      3 = qkv-fused: fp16 out, (acc+bias)*SCALE for global n<256
// Block 128x64, 8 warps (4M x 2N), warp 32x32, K-stage 64, 3-stage pipeline.
#define ASTR 72   // halves (144 B): ldmatrix 8-row access conflict-free
#define GEMM_SMEM (3 * (128 * ASTR + 64 * ASTR) * 2)

template<int EPI>
__global__ __launch_bounds__(256, 2) void gemm_f16(const __half* __restrict__ A,
                                                   const __half* __restrict__ Wt,
                                                   const float* __restrict__ bias,
                                                   void* __restrict__ Cv,
                                                   int M, int N, int K) {
    extern __shared__ __half smh[];
    __half (*As)[128][ASTR] = (__half (*)[128][ASTR])smh;
    __half (*Bs)[64][ASTR]  = (__half (*)[64][ASTR])(smh + 3 * 128 * ASTR);

    int tid = threadIdx.x;
    int lane = tid & 31, wid = tid >> 5;
    int wm = wid >> 1, wn = wid & 1;       // 4 (M) x 2 (N)
    int gr = lane >> 2, gc = lane & 3;
    int m0 = blockIdx.y * 128, n0 = blockIdx.x * 64;

    // gmem->smem: A 4 cp16/thread, B 2 cp16/thread (64 k-halves per stage)
    int a_r = tid >> 1, a_c = (tid & 1) * 32;
    int b_r = tid >> 2, b_c = (tid & 3) * 16;

    // ldmatrix lane addressing
    int lar = wm * 32 + (lane & 15);           // A row (+ mt*16)
    int lak = (lane >> 4) * 8;                 // A k-offset (+ kk*16)
    int lbr = wn * 32 + (lane >> 4) * 8 + (lane & 7);  // B row (+ ntp*16)
    int lbk = ((lane >> 3) & 1) * 8;           // B k-offset (+ kk*16)

    float acc[2][4][4];
#pragma unroll
    for (int mt = 0; mt < 2; mt++)
#pragma unroll
        for (int nt = 0; nt < 4; nt++)
#pragma unroll
            for (int r = 0; r < 4; r++) acc[mt][nt][r] = 0.f;

    int nc = K / 64;

    auto load_stage = [&](int st, int kb) {
#pragma unroll
        for (int j = 0; j < 4; j++)
            cp16(&As[st][a_r][a_c + j * 8], &A[(size_t)(m0 + a_r) * K + kb + a_c + j * 8]);
#pragma unroll
        for (int j = 0; j < 2; j++)
            cp16(&Bs[st][b_r][b_c + j * 8], &Wt[(size_t)(n0 + b_r) * K + kb + b_c + j * 8]);
        asm volatile("cp.async.commit_group;");
    };

    load_stage(0, 0);
    load_stage(1, 64);

    for (int c = 0; c < nc; c++) {
        if (c == nc - 1) asm volatile("cp.async.wait_group 0;");
        else             asm volatile("cp.async.wait_group 1;");
        __syncthreads();

        int st = c % 3;
#pragma unroll
        for (int kk = 0; kk < 4; kk++) {
            uint32_t aF[2][4], b01[4], b23[4];
            ldm4(aF[0], &As[st][lar][kk * 16 + lak]);
            ldm4(aF[1], &As[st][lar + 16][kk * 16 + lak]);
            ldm4(b01, &Bs[st][lbr][kk * 16 + lbk]);
            ldm4(b23, &Bs[st][lbr + 16][kk * 16 + lbk]);
#pragma unroll
            for (int mt = 0; mt < 2; mt++) {
                mma_f16(acc[mt][0], aF[mt], &b01[0]);
                mma_f16(acc[mt][1], aF[mt], &b01[2]);
                mma_f16(acc[mt][2], aF[mt], &b23[0]);
                mma_f16(acc[mt][3], aF[mt], &b23[2]);
            }
        }
        __syncthreads();
        if (c + 2 < nc) load_stage((c + 2) % 3, (c + 2) * 64);
    }

    // epilogue: acc layout c0=(gr,2gc) c1=(gr,2gc+1) c2=(gr+8,2gc) c3=(gr+8,2gc+1)
#pragma unroll
    for (int mt = 0; mt < 2; mt++) {
        int mA = m0 + wm * 32 + mt * 16 + gr;
#pragma unroll
        for (int nt = 0; nt < 4; nt++) {
            int n = n0 + wn * 32 + nt * 8 + 2 * gc;
            float bx = bias[n], by = bias[n + 1];
            float sc = (EPI == 3 && n < 256) ? SCALE : 1.0f;
#pragma unroll
            for (int h = 0; h < 2; h++) {
                int m = mA + h * 8;
                float vx = acc[mt][nt][2 * h + 0] + bx;
                float vy = acc[mt][nt][2 * h + 1] + by;
                if (EPI == 1) { vx = gelu_exact(vx); vy = gelu_exact(vy); }
                if (EPI == 3) { vx *= sc; vy *= sc; }
                if (EPI == 2) {
                    float2* cp = (float2*)&((float*)Cv)[(size_t)m * N + n];
                    float2 old = *cp;
                    *cp = make_float2(vx + old.x, vy + old.y);
                } else {
                    *(__half2*)&((__half*)Cv)[(size_t)m * N + n] = __floats2half2_rn(vx, vy);
                }
            }
        }
    }
}

// ---------------- fp16 flash attention: register-resident P (FA-2 style) ----------------
// 128-query tile, 64-key chunks, 8 warps. Warp w owns S rows [16w,16w+16).
// P stays in registers: QK accumulator layout == PV A-fragment layout after half2 packing.
// smem halves: Qs[128][40], Ks[2][64][40], Vs[2][64][40]  (no S buffer)
#define ATTN_SMEM ((128 * 40 + 2 * 64 * 40 + 2 * 64 * 40) * 2)

__global__ __launch_bounds__(256, 2) void attn_mma(const __half* __restrict__ QKVp,
                                                   const float* __restrict__ bias0,
                                                   const float* __restrict__ bias1,
                                                   __half* __restrict__ O,
                                                   int kvswap) {
    extern __shared__ __half smh[];
    __half (*Qs)[40]      = (__half (*)[40])smh;
    __half (*Ks)[64][40]  = (__half (*)[64][40])(smh + 128 * 40);
    __half (*Vs)[64][40]  = (__half (*)[64][40])(smh + 128 * 40 + 2 * 64 * 40);

    int t = threadIdx.x;
    int lane = t & 31, w = t >> 5;
    int gr = lane >> 2, gc = lane & 3;
    int qbase = blockIdx.x * 128;
    int h = blockIdx.y;
    int z = blockIdx.z;
    int s = z >> 2, b = z & 3;

    const __half* qptr = QKVp + (((size_t)(s * BB + b)) * NN + qbase) * QKV + h * HD;
    int ks = s ^ kvswap;
    const __half* kptr = QKVp + ((size_t)(ks * BB + b)) * NN * QKV + 256 + h * HD;
    const __half* vptr = QKVp + ((size_t)(ks * BB + b)) * NN * QKV + 512 + h * HD;
    const float* bias = kvswap ? nullptr : (s == 0 ? bias0 : bias1);
    const float* bptr = bias ? bias + (((size_t)(b * HH + h)) * NN + qbase) * NN : nullptr;

    {   // Q: 128x32 halves (already scaled by q-proj epilogue)
        int r = t >> 1, c = (t & 1) * 16;
        cp16(&Qs[r][c],     &qptr[(size_t)r * QKV + c]);
        cp16(&Qs[r][c + 8], &qptr[(size_t)r * QKV + c + 8]);
    }
    {   // K/V chunk 0
        int r = t >> 2, c = (t & 3) * 8;
        cp16(&Ks[0][r][c], &kptr[(size_t)r * QKV + c]);
        cp16(&Vs[0][r][c], &vptr[(size_t)r * QKV + c]);
    }
    asm volatile("cp.async.commit_group;");

    float m0 = -1e30f, m1 = -1e30f, l0 = 0.f, l1 = 0.f;
    float oa[4][4];
#pragma unroll
    for (int nt = 0; nt < 4; nt++)
#pragma unroll
        for (int r = 0; r < 4; r++) oa[nt][r] = 0.f;

    int r0 = 16 * w + gr, r1 = 16 * w + gr + 8;
    int lqr = 16 * w + (lane & 15);        // ldmatrix rows for Q frags
    int lqk = (lane >> 4) * 8;
    int lkr = (lane >> 4) * 8 + (lane & 7); // K frag rows (+ ntp*16)
    int lkk = ((lane >> 3) & 1) * 8;
    int lvr = lane & 15;                   // V x4.trans: rows (+ kk*16)
    int lvc = ((lane >> 4) & 1) * 8;       // V x4.trans: col group

    int buf = 0;
    for (int kc = 0; kc < 16; kc++) {
        int kb = kc * 64;
        if (kc + 1 < 16) {
            int kb2 = (kc + 1) * 64;
            int r = t >> 2, c = (t & 3) * 8;
            cp16(&Ks[buf ^ 1][r][c], &kptr[(size_t)(kb2 + r) * QKV + c]);
            cp16(&Vs[buf ^ 1][r][c], &vptr[(size_t)(kb2 + r) * QKV + c]);
            asm volatile("cp.async.commit_group;");
            asm volatile("cp.async.wait_group 1;");
        } else {
            asm volatile("cp.async.wait_group 0;");
        }
        __syncthreads();

        // ---- S = Q @ K^T (+bias) : m16 x n64, k=32 ----
        float sacc[8][4];
#pragma unroll
        for (int nt = 0; nt < 8; nt++)
#pragma unroll
            for (int r = 0; r < 4; r++) sacc[nt][r] = 0.f;

#pragma unroll
        for (int kk = 0; kk < 2; kk++) {
            uint32_t aF[4];
            ldm4(aF, &Qs[lqr][kk * 16 + lqk]);
#pragma unroll
            for (int ntp = 0; ntp < 4; ntp++) {
                uint32_t bP[4];
                ldm4(bP, &Ks[buf][ntp * 16 + lkr][kk * 16 + lkk]);
                mma_f16(sacc[ntp * 2 + 0], aF, &bP[0]);
                mma_f16(sacc[ntp * 2 + 1], aF, &bP[2]);
            }
        }
        if (bptr) {
#pragma unroll
            for (int nt = 0; nt < 8; nt++) {
                int col = kb + nt * 8 + 2 * gc;
                float2 u0 = *(const float2*)&bptr[(size_t)r0 * NN + col];
                float2 u1 = *(const float2*)&bptr[(size_t)r1 * NN + col];
                sacc[nt][0] += u0.x; sacc[nt][1] += u0.y;
                sacc[nt][2] += u1.x; sacc[nt][3] += u1.y;
            }
        }

        // ---- online softmax (rows r0, r1; quad-local) + register P pack ----
        float cm0 = -1e30f, cm1 = -1e30f;
#pragma unroll
        for (int nt = 0; nt < 8; nt++) {
            cm0 = fmaxf(cm0, fmaxf(sacc[nt][0], sacc[nt][1]));
            cm1 = fmaxf(cm1, fmaxf(sacc[nt][2], sacc[nt][3]));
        }
        cm0 = fmaxf(cm0, __shfl_xor_sync(0xffffffffu, cm0, 1));
        cm0 = fmaxf(cm0, __shfl_xor_sync(0xffffffffu, cm0, 2));
        cm1 = fmaxf(cm1, __shfl_xor_sync(0xffffffffu, cm1, 1));
        cm1 = fmaxf(cm1, __shfl_xor_sync(0xffffffffu, cm1, 2));
        float nm0 = fmaxf(m0, cm0), nm1 = fmaxf(m1, cm1);
        float f0 = __expf(m0 - nm0), f1 = __expf(m1 - nm1);
        float sum0 = 0.f, sum1 = 0.f;
        uint32_t pA[4][4];   // [kk16][frag]: PV A-fragments, packed in registers
#pragma unroll
        for (int nt = 0; nt < 8; nt++) {
            float p0 = __expf(sacc[nt][0] - nm0);
            float p1 = __expf(sacc[nt][1] - nm0);
            float p2 = __expf(sacc[nt][2] - nm1);
            float p3 = __expf(sacc[nt][3] - nm1);
            sum0 += p0 + p1; sum1 += p2 + p3;
            pA[nt >> 1][(nt & 1) * 2 + 0] = half2_bits(__floats2half2_rn(p0, p1));
            pA[nt >> 1][(nt & 1) * 2 + 1] = half2_bits(__floats2half2_rn(p2, p3));
        }
        sum0 += __shfl_xor_sync(0xffffffffu, sum0, 1);
        sum0 += __shfl_xor_sync(0xffffffffu, sum0, 2);
        sum1 += __shfl_xor_sync(0xffffffffu, sum1, 1);
        sum1 += __shfl_xor_sync(0xffffffffu, sum1, 2);
        l0 = l0 * f0 + sum0; m0 = nm0;
        l1 = l1 * f1 + sum1; m1 = nm1;
#pragma unroll
        for (int nt = 0; nt < 4; nt++) {
            oa[nt][0] *= f0; oa[nt][1] *= f0;
            oa[nt][2] *= f1; oa[nt][3] *= f1;
        }

        // ---- O += P @ V : m16 x n32, k=64 (P from registers, V via x4.trans) ----
#pragma unroll
        for (int kk = 0; kk < 4; kk++) {
            const __half* vb = &Vs[buf][kk * 16 + lvr][lvc];
            uint32_t b03[4], b47[4];
            ldm4t(b03, vb);        // B-frags: n0-7 (b03[0,1]), n8-15 (b03[2,3])
            ldm4t(b47, vb + 16);   // B-frags: n16-23, n24-31
            mma_f16(oa[0], pA[kk], &b03[0]);
            mma_f16(oa[1], pA[kk], &b03[2]);
            mma_f16(oa[2], pA[kk], &b47[0]);
            mma_f16(oa[3], pA[kk], &b47[2]);
        }
        __syncthreads();
        buf ^= 1;
    }

    float inv0 = 1.f / l0, inv1 = 1.f / l1;
    __half* obase = O + (((size_t)(s * BB + b)) * NN + qbase) * DIM + h * HD;
#pragma unroll
    for (int nt = 0; nt < 4; nt++) {
        int col = nt * 8 + 2 * gc;
        *(__half2*)&obase[(size_t)r0 * DIM + col] =
            __floats2half2_rn(oa[nt][0] * inv0, oa[nt][1] * inv0);
        *(__half2*)&obase[(size_t)r1 * DIM + col] =
            __floats2half2_rn(oa[nt][2] * inv1, oa[nt][3] * inv1);
    }
}

// ---------------- host orchestration ----------------
static void launch_gemm(int epi, const __half* A, const __half* Wt, const float* bias,
                        void* C, int M, int N, int K) {
    dim3 g(N / 64, M / 128);
    if (epi == 0)      gemm_f16<0><<<g, 256, GEMM_SMEM>>>(A, Wt, bias, C, M, N, K);
    else if (epi == 1) gemm_f16<1><<<g, 256, GEMM_SMEM>>>(A, Wt, bias, C, M, N, K);
    else if (epi == 2) gemm_f16<2><<<g, 256, GEMM_SMEM>>>(A, Wt, bias, C, M, N, K);
    else               gemm_f16<3><<<g, 256, GEMM_SMEM>>>(A, Wt, bias, C, M, N, K);
}

extern "C" void kernel_launch(void* const* d_in, const int* in_sizes, int n_in,
                              void* d_out, int out_size) {
    const float* src_feats = (const float*)d_in[0];
    const float* tgt_feats = (const float*)d_in[1];
    const float* src_bias  = (const float*)d_in[2];
    const float* tgt_bias  = (const float*)d_in[3];
    const float* sa_q_w = (const float*)d_in[4];  const float* sa_q_b = (const float*)d_in[5];
    const float* sa_k_w = (const float*)d_in[6];  const float* sa_k_b = (const float*)d_in[7];
    const float* sa_v_w = (const float*)d_in[8];  const float* sa_v_b = (const float*)d_in[9];
    const float* sa_o_w = (const float*)d_in[10]; const float* sa_o_b = (const float*)d_in[11];
    const float* ca_q_w = (const float*)d_in[12]; const float* ca_q_b = (const float*)d_in[13];
    const float* ca_k_w = (const float*)d_in[14]; const float* ca_k_b = (const float*)d_in[15];
    const float* ca_v_w = (const float*)d_in[16]; const float* ca_v_b = (const float*)d_in[17];
    const float* ca_o_w = (const float*)d_in[18]; const float* ca_o_b = (const float*)d_in[19];
    const float* ln_sa_g = (const float*)d_in[20]; const float* ln_sa_b = (const float*)d_in[21];
    const float* ln_ca_g = (const float*)d_in[22]; const float* ln_ca_b = (const float*)d_in[23];
    const float* ln_ff_g = (const float*)d_in[24]; const float* ln_ff_b = (const float*)d_in[25];
    const float* ffn_w1 = (const float*)d_in[26]; const float* ffn_b1 = (const float*)d_in[27];
    const float* ffn_w2 = (const float*)d_in[28]; const float* ffn_b2 = (const float*)d_in[29];

    float* res = (float*)d_out; // [2, B, N, DIM]

    cudaFuncSetAttribute(gemm_f16<0>, cudaFuncAttributeMaxDynamicSharedMemorySize, GEMM_SMEM);
    cudaFuncSetAttribute(gemm_f16<1>, cudaFuncAttributeMaxDynamicSharedMemorySize, GEMM_SMEM);
    cudaFuncSetAttribute(gemm_f16<2>, cudaFuncAttributeMaxDynamicSharedMemorySize, GEMM_SMEM);
    cudaFuncSetAttribute(gemm_f16<3>, cudaFuncAttributeMaxDynamicSharedMemorySize, GEMM_SMEM);
    cudaFuncSetAttribute(attn_mma,    cudaFuncAttributeMaxDynamicSharedMemorySize, ATTN_SMEM);

    void *p_xn, *p_qkv, *p_ao, *p_h, *p_wt, *p_bq;
    cudaGetSymbolAddress(&p_xn,  g_xn);
    cudaGetSymbolAddress(&p_qkv, g_qkv);
    cudaGetSymbolAddress(&p_ao,  g_ao);
    cudaGetSymbolAddress(&p_h,   g_hh);
    cudaGetSymbolAddress(&p_wt,  g_wt);
    cudaGetSymbolAddress(&p_bq,  g_bqkv);
    __half* xn  = (__half*)p_xn;
    __half* qkv = (__half*)p_qkv;
    __half* ao  = (__half*)p_ao;
    __half* hb  = (__half*)p_h;
    __half* wt  = (__half*)p_wt;
    float*  bq  = (float*)p_bq;

    __half* wt_saqkv = wt;                        // [768][256]
    __half* wt_caqkv = wt + 196608;               // [768][256]
    __half* wt_sao   = wt + 393216;               // [256][256]
    __half* wt_cao   = wt + 458752;               // [256][256]
    __half* wt_w1    = wt + 524288;               // [1024][256]
    __half* wt_w2    = wt + 786432;               // [256][1024]

    WList wl;
    const float* srcs[10] = {sa_q_w, sa_k_w, sa_v_w, ca_q_w, ca_k_w, ca_v_w,
                             sa_o_w, ca_o_w, ffn_w1, ffn_w2};
    __half* dsts[10] = {wt_saqkv, wt_saqkv + 256 * 256, wt_saqkv + 512 * 256,
                        wt_caqkv, wt_caqkv + 256 * 256, wt_caqkv + 512 * 256,
                        wt_sao, wt_cao, wt_w1, wt_w2};
    int Ksz[10] = {256, 256, 256, 256, 256, 256, 256, 256, 256, 1024};
    int Nsz[10] = {256, 256, 256, 256, 256, 256, 256, 256, 1024, 256};
    for (int i = 0; i < 10; i++) { wl.src[i] = srcs[i]; wl.dst[i] = dsts[i]; wl.K[i] = Ksz[i]; wl.N[i] = Nsz[i]; }
    wcvt_kernel<<<dim3(32, 32, 10), 256>>>(wl);
    bias_fuse_kernel<<<2, QKV>>>(sa_q_b, sa_k_b, sa_v_b, ca_q_b, ca_k_b, ca_v_b, bq);

    copy_feats_kernel<<<STREAM_ELEMS / 4 / 256, 256>>>(
        (const float4*)src_feats, (const float4*)tgt_feats, (float4*)res);

    dim3 agrid(NN / 128, HH, 2 * BB);

    // ---- 1. geometric self-attention ----
    ln_kernel<<<MROWS, 256>>>(res, ln_sa_g, ln_sa_b, xn);
    launch_gemm(3, xn, wt_saqkv, bq, qkv, MROWS, QKV, DIM);
    attn_mma<<<agrid, 256, ATTN_SMEM>>>(qkv, src_bias, tgt_bias, ao, 0);
    launch_gemm(2, ao, wt_sao, sa_o_b, res, MROWS, DIM, DIM);

    // ---- 2. cross-attention ----
    ln_kernel<<<MROWS, 256>>>(res, ln_ca_g, ln_ca_b, xn);
    launch_gemm(3, xn, wt_caqkv, bq + QKV, qkv, MROWS, QKV, DIM);
    attn_mma<<<agrid, 256, ATTN_SMEM>>>(qkv, nullptr, nullptr, ao, 1);
    launch_gemm(2, ao, wt_cao, ca_o_b, res, MROWS, DIM, DIM);

    // ---- 3. FFN ----
    ln_kernel<<<MROWS, 256>>>(res, ln_ff_g, ln_ff_b, xn);
    launch_gemm(1, xn, wt_w1, ffn_b1, hb, MROWS, FFN_DIM, DIM);
    launch_gemm(2, hb, wt_w2, ffn_b2, res, MROWS, DIM, FFN_DIM);
}